// round 3
// baseline (speedup 1.0000x reference)
#include <cuda_runtime.h>
#include <cstdint>

#define B_  2
#define L_  2048
#define DK_ 512
#define H_  8
#define DH_ 64
#define BH_ (B_*H_)
#define STR 68          // smem stride (≡4 mod 32) for 64-wide tiles
#define PSTR 132        // smem stride for 128-wide tiles

// ---- device scratch ----
__device__ float g_Q[BH_*L_*DH_];
__device__ float g_K[BH_*L_*DH_];
__device__ float g_V[BH_*L_*DH_];
__device__ float g_Wt[3*H_*DH_*DK_];   // [mat][h][e][d]
__device__ float g_Vt[BH_*DH_*L_];     // [bh][e][k] = V[k][e] * Dinv[k]
__device__ float g_Dinv[BH_*L_];

__device__ __forceinline__ float cvt_tf32(float x) {
    uint32_t r; asm("cvt.rna.tf32.f32 %0, %1;" : "=r"(r) : "f"(x));
    return __uint_as_float(r);
}
__device__ __forceinline__ float4 cvt4(float4 v) {
    return make_float4(cvt_tf32(v.x), cvt_tf32(v.y), cvt_tf32(v.z), cvt_tf32(v.w));
}
__device__ __forceinline__ void mma_tf32(float* d, float a0, float a1, float a2, float a3,
                                         float b0, float b1) {
    asm volatile("mma.sync.aligned.m16n8k8.row.col.f32.tf32.tf32.f32 "
                 "{%0,%1,%2,%3}, {%4,%5,%6,%7}, {%8,%9}, {%0,%1,%2,%3};"
                 : "+f"(d[0]), "+f"(d[1]), "+f"(d[2]), "+f"(d[3])
                 : "r"(__float_as_uint(a0)), "r"(__float_as_uint(a1)),
                   "r"(__float_as_uint(a2)), "r"(__float_as_uint(a3)),
                   "r"(__float_as_uint(b0)), "r"(__float_as_uint(b1)));
}

// ---------------------------------------------------------------------------
__global__ __launch_bounds__(256) void wprep_kernel(
    const float* __restrict__ wq, const float* __restrict__ wk,
    const float* __restrict__ wv)
{
    __shared__ float t[32][33];
    const int mh  = blockIdx.z;
    const int mat = mh / H_, h = mh % H_;
    const float* W = (mat == 0) ? wq : (mat == 1) ? wk : wv;
    const int d0 = blockIdx.x * 32, e0 = blockIdx.y * 32;
    const int tx = threadIdx.x & 31, ty = threadIdx.x >> 5;
#pragma unroll
    for (int i = 0; i < 32; i += 8)
        t[ty + i][tx] = W[((size_t)h * DK_ + d0 + ty + i) * DH_ + e0 + tx];
    __syncthreads();
#pragma unroll
    for (int i = 0; i < 32; i += 8)
        g_Wt[((size_t)mh * DH_ + e0 + ty + i) * DK_ + d0 + tx] = t[tx][ty + i];
}

// ---------------------------------------------------------------------------
// Projections: O[128 l x 64 e] = X[128 x 512] * W[512 x 64]
// ---------------------------------------------------------------------------
__global__ __launch_bounds__(128) void proj_kernel(
    const float* __restrict__ q_in, const float* __restrict__ k_in,
    const float* __restrict__ v_in)
{
    extern __shared__ float sm[];
    float* Xs = sm;             // [128][STR]
    float* Ws = sm + 128*STR;   // [64][STR]

    const int mat = blockIdx.z, bh = blockIdx.y, l0 = blockIdx.x * 128;
    const int b = bh / H_, h = bh % H_;
    const float* X  = (mat == 0) ? q_in : (mat == 1) ? k_in : v_in;
    const float* Wt = g_Wt + ((size_t)(mat * H_ + h)) * DH_ * DK_;
    float*       O  = (mat == 0) ? g_Q : (mat == 1) ? g_K : g_V;

    const int tid = threadIdx.x, lane = tid & 31, wid = tid >> 5;
    const int wm = wid >> 1, wn = wid & 1;
    const int grp = lane >> 2, cp = lane & 3;

    float acc[4][4][4];
#pragma unroll
    for (int i = 0; i < 4; ++i)
#pragma unroll
        for (int j = 0; j < 4; ++j)
#pragma unroll
            for (int c = 0; c < 4; ++c) acc[i][j][c] = 0.f;

    for (int d0 = 0; d0 < DK_; d0 += 64) {
#pragma unroll
        for (int it = 0; it < 16; ++it) {
            int f = it * 128 + tid;
            int r = f >> 4, c4 = f & 15;
            float4 v = *(const float4*)(X + ((size_t)(b * L_ + l0 + r)) * DK_ + d0 + c4 * 4);
            *(float4*)(Xs + r * STR + c4 * 4) = cvt4(v);
        }
#pragma unroll
        for (int it = 0; it < 8; ++it) {
            int f = it * 128 + tid;
            int r = f >> 4, c4 = f & 15;
            float4 v = *(const float4*)(Wt + (size_t)r * DK_ + d0 + c4 * 4);
            *(float4*)(Ws + r * STR + c4 * 4) = cvt4(v);
        }
        __syncthreads();
#pragma unroll
        for (int ks = 0; ks < 8; ++ks) {
            float a[4][4];
#pragma unroll
            for (int mt = 0; mt < 4; ++mt) {
                const float* base = Xs + (wm*64 + mt*16 + grp) * STR + ks*8 + cp;
                a[mt][0] = base[0];       a[mt][2] = base[4];
                a[mt][1] = base[8*STR];   a[mt][3] = base[8*STR + 4];
            }
            float bf[4][2];
#pragma unroll
            for (int nt = 0; nt < 4; ++nt) {
                const float* base = Ws + (wn*32 + nt*8 + grp) * STR + ks*8 + cp;
                bf[nt][0] = base[0];      bf[nt][1] = base[4];
            }
#pragma unroll
            for (int mt = 0; mt < 4; ++mt)
#pragma unroll
                for (int nt = 0; nt < 4; ++nt)
                    mma_tf32(acc[mt][nt], a[mt][0], a[mt][1], a[mt][2], a[mt][3],
                             bf[nt][0], bf[nt][1]);
        }
        __syncthreads();
    }
#pragma unroll
    for (int mt = 0; mt < 4; ++mt) {
        int l = l0 + wm*64 + mt*16 + grp;
#pragma unroll
        for (int nt = 0; nt < 4; ++nt) {
            int e = wn*32 + nt*8 + cp*2;
            *(float2*)(O + ((size_t)bh*L_ + l)*DH_ + e)     = make_float2(acc[mt][nt][0], acc[mt][nt][1]);
            *(float2*)(O + ((size_t)bh*L_ + l + 8)*DH_ + e) = make_float2(acc[mt][nt][2], acc[mt][nt][3]);
        }
    }
}

// ---------------------------------------------------------------------------
// Pass A: D[k] = sum_q exp(S[q,k]).  Block: 128 k-columns, all 2048 q.
// K tile resident; Q tiles streamed with register prefetch. Writes g_Dinv.
// ---------------------------------------------------------------------------
__global__ __launch_bounds__(256) void passA_kernel()
{
    extern __shared__ float sm[];
    float* Ks = sm;             // [128][STR]
    float* Qs = sm + 128*STR;   // [128][STR]

    const int bh = blockIdx.y, k0 = blockIdx.x * 128;
    const int tid = threadIdx.x, lane = tid & 31, wid = tid >> 5;
    const int wm = wid >> 2, wn = wid & 3;      // 2 x 4 warps over (q64, k32)
    const int grp = lane >> 2, cp = lane & 3;

    // K tile (resident)
#pragma unroll
    for (int it = 0; it < 8; ++it) {
        int f = it * 256 + tid;
        int r = f >> 4, c4 = f & 15;
        float4 v = *(const float4*)(g_K + ((size_t)bh*L_ + k0 + r)*DH_ + c4*4);
        *(float4*)(Ks + r*STR + c4*4) = cvt4(v);
    }

    // prefetch q-tile 0 into regs
    float4 pre[8];
#pragma unroll
    for (int it = 0; it < 8; ++it) {
        int f = it * 256 + tid;
        int r = f >> 4, c4 = f & 15;
        pre[it] = *(const float4*)(g_Q + ((size_t)bh*L_ + r)*DH_ + c4*4);
    }

    float cs0[4] = {0,0,0,0}, cs1[4] = {0,0,0,0};
    const float rsc = 0.02209708691207961f;  // 1/sqrt(2048)

    for (int qt = 0; qt < 16; ++qt) {
#pragma unroll
        for (int it = 0; it < 8; ++it) {
            int f = it * 256 + tid;
            int r = f >> 4, c4 = f & 15;
            *(float4*)(Qs + r*STR + c4*4) = cvt4(pre[it]);
        }
        __syncthreads();
        if (qt < 15) {
            int q0n = (qt + 1) * 128;
#pragma unroll
            for (int it = 0; it < 8; ++it) {
                int f = it * 256 + tid;
                int r = f >> 4, c4 = f & 15;
                pre[it] = *(const float4*)(g_Q + ((size_t)bh*L_ + q0n + r)*DH_ + c4*4);
            }
        }

        float acc[4][4][4];
#pragma unroll
        for (int i = 0; i < 4; ++i)
#pragma unroll
            for (int j = 0; j < 4; ++j)
#pragma unroll
                for (int c = 0; c < 4; ++c) acc[i][j][c] = 0.f;

#pragma unroll
        for (int ks = 0; ks < 8; ++ks) {
            float a[4][4];
#pragma unroll
            for (int mt = 0; mt < 4; ++mt) {
                const float* base = Qs + (wm*64 + mt*16 + grp) * STR + ks*8 + cp;
                a[mt][0] = base[0];      a[mt][2] = base[4];
                a[mt][1] = base[8*STR];  a[mt][3] = base[8*STR + 4];
            }
            float bf[4][2];
#pragma unroll
            for (int nt = 0; nt < 4; ++nt) {
                const float* base = Ks + (wn*32 + nt*8 + grp) * STR + ks*8 + cp;
                bf[nt][0] = base[0];     bf[nt][1] = base[4];
            }
#pragma unroll
            for (int mt = 0; mt < 4; ++mt)
#pragma unroll
                for (int nt = 0; nt < 4; ++nt)
                    mma_tf32(acc[mt][nt], a[mt][0], a[mt][1], a[mt][2], a[mt][3],
                             bf[nt][0], bf[nt][1]);
        }
#pragma unroll
        for (int mt = 0; mt < 4; ++mt)
#pragma unroll
            for (int nt = 0; nt < 4; ++nt) {
                cs0[nt] += __expf(acc[mt][nt][0] * rsc) + __expf(acc[mt][nt][2] * rsc);
                cs1[nt] += __expf(acc[mt][nt][1] * rsc) + __expf(acc[mt][nt][3] * rsc);
            }
        __syncthreads();
    }

    // reduce over grp within warp
#pragma unroll
    for (int nt = 0; nt < 4; ++nt) {
        cs0[nt] += __shfl_xor_sync(0xffffffffu, cs0[nt], 4);
        cs0[nt] += __shfl_xor_sync(0xffffffffu, cs0[nt], 8);
        cs0[nt] += __shfl_xor_sync(0xffffffffu, cs0[nt], 16);
        cs1[nt] += __shfl_xor_sync(0xffffffffu, cs1[nt], 4);
        cs1[nt] += __shfl_xor_sync(0xffffffffu, cs1[nt], 8);
        cs1[nt] += __shfl_xor_sync(0xffffffffu, cs1[nt], 16);
    }
    float* Cs = sm;  // reuse (after sync above)
    if (lane < 4) {
#pragma unroll
        for (int nt = 0; nt < 4; ++nt) {
            Cs[wm*128 + wn*32 + nt*8 + lane*2]     = cs0[nt];
            Cs[wm*128 + wn*32 + nt*8 + lane*2 + 1] = cs1[nt];
        }
    }
    __syncthreads();
    if (tid < 128)
        g_Dinv[bh*L_ + k0 + tid] = 1.0f / (Cs[tid] + Cs[128 + tid]);
}

// ---------------------------------------------------------------------------
// V transpose + scale: g_Vt[bh][e][k] = V[bh][k][e] * Dinv[bh][k]
// ---------------------------------------------------------------------------
__global__ __launch_bounds__(256) void vprep_kernel()
{
    __shared__ float t[32][33];
    const int bh = blockIdx.z;
    const int k0 = blockIdx.x * 32, e0 = blockIdx.y * 32;
    const int tx = threadIdx.x & 31, ty = threadIdx.x >> 5;
#pragma unroll
    for (int i = 0; i < 32; i += 8) {
        int k = k0 + ty + i;
        t[ty + i][tx] = g_V[((size_t)bh*L_ + k)*DH_ + e0 + tx] * g_Dinv[bh*L_ + k];
    }
    __syncthreads();
#pragma unroll
    for (int i = 0; i < 32; i += 8)
        g_Vt[((size_t)bh*DH_ + e0 + ty + i)*L_ + k0 + tx] = t[tx][ty + i];
}

// ---------------------------------------------------------------------------
// Pass B: out[128q x 64e] = sum_k exp(S[q,k]) * Vt[e,k].
// Recompute S per 128-k tile; P lives only in smem (aliased over K buffer).
// ---------------------------------------------------------------------------
__global__ __launch_bounds__(256) void passB_kernel(float* __restrict__ out)
{
    extern __shared__ float sm[];
    float* Qs = sm;                         // [128][STR]    8704 floats
    float* PB = sm + 128*STR;               // Ks [128][STR] aliased by Ps [128][PSTR] (16896)
    float* Vs = sm + 128*STR + 128*PSTR;    // [64][PSTR]    8448 floats

    const int bh = blockIdx.y, q0 = blockIdx.x * 128;
    const int b = bh / H_, h = bh % H_;
    const int tid = threadIdx.x, lane = tid & 31, wid = tid >> 5;
    const int wm = wid >> 2, wn = wid & 3;      // S: 2x4 over (q64, k32)
    const int wm2 = wid >> 1, wn2 = wid & 1;    // PV: 4x2 over (q32, e32)
    const int grp = lane >> 2, cp = lane & 3;

    // Q tile resident
#pragma unroll
    for (int it = 0; it < 8; ++it) {
        int f = it * 256 + tid;
        int r = f >> 4, c4 = f & 15;
        float4 v = *(const float4*)(g_Q + ((size_t)bh*L_ + q0 + r)*DH_ + c4*4);
        *(float4*)(Qs + r*STR + c4*4) = cvt4(v);
    }

    float acc_o[2][4][4];
#pragma unroll
    for (int i = 0; i < 2; ++i)
#pragma unroll
        for (int j = 0; j < 4; ++j)
#pragma unroll
            for (int c = 0; c < 4; ++c) acc_o[i][j][c] = 0.f;

    const float rsc = 0.02209708691207961f;

    for (int k0 = 0; k0 < L_; k0 += 128) {
        // load K tile into PB (stride STR) and Vt tile into Vs
#pragma unroll
        for (int it = 0; it < 8; ++it) {
            int f = it * 256 + tid;
            int r = f >> 4, c4 = f & 15;
            float4 v = *(const float4*)(g_K + ((size_t)bh*L_ + k0 + r)*DH_ + c4*4);
            *(float4*)(PB + r*STR + c4*4) = cvt4(v);
        }
#pragma unroll
        for (int it = 0; it < 8; ++it) {
            int f = it * 256 + tid;
            int r = f >> 5, c4 = f & 31;
            float4 v = *(const float4*)(g_Vt + ((size_t)bh*DH_ + r)*L_ + k0 + c4*4);
            *(float4*)(Vs + r*PSTR + c4*4) = cvt4(v);
        }
        __syncthreads();   // (a) tiles visible (also protects Ps of prev iter)

        // S = Q K^T  (128 x 128)
        float acc[4][4][4];
#pragma unroll
        for (int i = 0; i < 4; ++i)
#pragma unroll
            for (int j = 0; j < 4; ++j)
#pragma unroll
                for (int c = 0; c < 4; ++c) acc[i][j][c] = 0.f;

#pragma unroll
        for (int ks = 0; ks < 8; ++ks) {
            float a[4][4];
#pragma unroll
            for (int mt = 0; mt < 4; ++mt) {
                const float* base = Qs + (wm*64 + mt*16 + grp) * STR + ks*8 + cp;
                a[mt][0] = base[0];      a[mt][2] = base[4];
                a[mt][1] = base[8*STR];  a[mt][3] = base[8*STR + 4];
            }
            float bf[4][2];
#pragma unroll
            for (int nt = 0; nt < 4; ++nt) {
                const float* base = PB + (wn*32 + nt*8 + grp) * STR + ks*8 + cp;
                bf[nt][0] = base[0];     bf[nt][1] = base[4];
            }
#pragma unroll
            for (int mt = 0; mt < 4; ++mt)
#pragma unroll
                for (int nt = 0; nt < 4; ++nt)
                    mma_tf32(acc[mt][nt], a[mt][0], a[mt][1], a[mt][2], a[mt][3],
                             bf[nt][0], bf[nt][1]);
        }
        __syncthreads();   // (b) everyone done reading Ks before Ps overwrite

        // exp -> Ps (stride PSTR over PB region)
#pragma unroll
        for (int mt = 0; mt < 4; ++mt) {
            int ql = wm*64 + mt*16 + grp;
#pragma unroll
            for (int nt = 0; nt < 4; ++nt) {
                int kl = wn*32 + nt*8 + cp*2;
                float p0 = cvt_tf32(__expf(acc[mt][nt][0] * rsc));
                float p1 = cvt_tf32(__expf(acc[mt][nt][1] * rsc));
                float p2 = cvt_tf32(__expf(acc[mt][nt][2] * rsc));
                float p3 = cvt_tf32(__expf(acc[mt][nt][3] * rsc));
                *(float2*)(PB + ql*PSTR + kl)       = make_float2(p0, p1);
                *(float2*)(PB + (ql+8)*PSTR + kl)   = make_float2(p2, p3);
            }
        }
        __syncthreads();   // (c) Ps visible

        // out += Ps * Vs   (A = Ps 128q x 128k, B = Vs [e][k])
#pragma unroll
        for (int ks = 0; ks < 16; ++ks) {
            float a[2][4];
#pragma unroll
            for (int mt = 0; mt < 2; ++mt) {
                const float* base = PB + (wm2*32 + mt*16 + grp) * PSTR + ks*8 + cp;
                a[mt][0] = base[0];       a[mt][2] = base[4];
                a[mt][1] = base[8*PSTR];  a[mt][3] = base[8*PSTR + 4];
            }
            float bf[4][2];
#pragma unroll
            for (int nt = 0; nt < 4; ++nt) {
                const float* base = Vs + (wn2*32 + nt*8 + grp) * PSTR + ks*8 + cp;
                bf[nt][0] = base[0];      bf[nt][1] = base[4];
            }
#pragma unroll
            for (int mt = 0; mt < 2; ++mt)
#pragma unroll
                for (int nt = 0; nt < 4; ++nt)
                    mma_tf32(acc_o[mt][nt], a[mt][0], a[mt][1], a[mt][2], a[mt][3],
                             bf[nt][0], bf[nt][1]);
        }
        __syncthreads();   // (d) Ps reads done before next iter's K load
    }

#pragma unroll
    for (int mt = 0; mt < 2; ++mt) {
        int q = q0 + wm2*32 + mt*16 + grp;
#pragma unroll
        for (int nt = 0; nt < 4; ++nt) {
            int e = wn2*32 + nt*8 + cp*2;
            *(float2*)(out + ((size_t)b*L_ + q)*(H_*DH_) + h*DH_ + e) =
                make_float2(acc_o[mt][nt][0], acc_o[mt][nt][1]);
            *(float2*)(out + ((size_t)b*L_ + q + 8)*(H_*DH_) + h*DH_ + e) =
                make_float2(acc_o[mt][nt][2], acc_o[mt][nt][3]);
        }
    }
}

// ---------------------------------------------------------------------------
extern "C" void kernel_launch(void* const* d_in, const int* in_sizes, int n_in,
                              void* d_out, int out_size)
{
    const float* keys    = (const float*)d_in[0];
    const float* queries = (const float*)d_in[1];
    const float* values  = (const float*)d_in[2];
    const float* WQ      = (const float*)d_in[3];
    const float* WK      = (const float*)d_in[4];
    const float* WV      = (const float*)d_in[5];
    float* out = (float*)d_out;

    const int PP_SMEM = (192*STR) * 4;                        // proj: 52224
    const int PA_SMEM = (256*STR) * 4;                        // passA: 69632
    const int PB_SMEM = (128*STR + 128*PSTR + 64*PSTR) * 4;   // passB: 136192

    cudaFuncSetAttribute(proj_kernel,  cudaFuncAttributeMaxDynamicSharedMemorySize, PP_SMEM);
    cudaFuncSetAttribute(passA_kernel, cudaFuncAttributeMaxDynamicSharedMemorySize, PA_SMEM);
    cudaFuncSetAttribute(passB_kernel, cudaFuncAttributeMaxDynamicSharedMemorySize, PB_SMEM);

    wprep_kernel<<<dim3(DK_/32, DH_/32, 24), 256>>>(WQ, WK, WV);
    proj_kernel<<<dim3(L_/128, BH_, 3), 128, PP_SMEM>>>(queries, keys, values);
    passA_kernel<<<dim3(L_/128, BH_), 256, PA_SMEM>>>();
    vprep_kernel<<<dim3(L_/32, DH_/32, BH_), 256>>>();
    passB_kernel<<<dim3(L_/128, BH_), 256, PB_SMEM>>>(out);
}

// round 4
// speedup vs baseline: 1.2735x; 1.2735x over previous
#include <cuda_runtime.h>
#include <cstdint>

#define B_  2
#define L_  2048
#define DK_ 512
#define H_  8
#define DH_ 64
#define BH_ (B_*H_)
#define QB_ (L_/128)
#define STR 68          // smem row stride in floats (≡4 mod 32; 272B, 16B-aligned)

// ---- device scratch (tf32-rounded where noted) ----
__device__ __align__(256) float g_Q[BH_*L_*DH_];        // tf32
__device__ __align__(256) float g_K[BH_*L_*DH_];        // tf32
__device__ __align__(256) float g_V[BH_*L_*DH_];        // raw fp32
__device__ __align__(256) float g_Wt[3*H_*DH_*DK_];     // tf32, [mat][h][e][d]
__device__ __align__(256) float g_Vt[BH_*DH_*L_];       // tf32, [bh][e][k] = V*Dinv
__device__ __align__(256) float g_P[(size_t)BH_*L_*L_]; // tf32, exp(S/sqrt(Lk))
__device__ __align__(256) float g_Dp[BH_*QB_*L_];
__device__ __align__(256) float g_Dinv[BH_*L_];

__device__ __forceinline__ float cvt_tf32(float x) {
    uint32_t r; asm("cvt.rna.tf32.f32 %0, %1;" : "=r"(r) : "f"(x));
    return __uint_as_float(r);
}
__device__ __forceinline__ float4 cvt4(float4 v) {
    return make_float4(cvt_tf32(v.x), cvt_tf32(v.y), cvt_tf32(v.z), cvt_tf32(v.w));
}
__device__ __forceinline__ void mma_tf32(float* d, float a0, float a1, float a2, float a3,
                                         float b0, float b1) {
    asm volatile("mma.sync.aligned.m16n8k8.row.col.f32.tf32.tf32.f32 "
                 "{%0,%1,%2,%3}, {%4,%5,%6,%7}, {%8,%9}, {%0,%1,%2,%3};"
                 : "+f"(d[0]), "+f"(d[1]), "+f"(d[2]), "+f"(d[3])
                 : "r"(__float_as_uint(a0)), "r"(__float_as_uint(a1)),
                   "r"(__float_as_uint(a2)), "r"(__float_as_uint(a3)),
                   "r"(__float_as_uint(b0)), "r"(__float_as_uint(b1)));
}
__device__ __forceinline__ void cp16(float* dst_smem, const float* src) {
    uint32_t d = (uint32_t)__cvta_generic_to_shared(dst_smem);
    asm volatile("cp.async.cg.shared.global [%0], [%1], 16;" :: "r"(d), "l"(src));
}
__device__ __forceinline__ void cp_commit() { asm volatile("cp.async.commit_group;"); }
template<int N> __device__ __forceinline__ void cp_wait() {
    asm volatile("cp.async.wait_group %0;" :: "n"(N));
}

// ---------------------------------------------------------------------------
__global__ __launch_bounds__(256) void wprep_kernel(
    const float* __restrict__ wq, const float* __restrict__ wk,
    const float* __restrict__ wv)
{
    __shared__ float t[32][33];
    const int mh  = blockIdx.z;
    const int mat = mh / H_, h = mh % H_;
    const float* W = (mat == 0) ? wq : (mat == 1) ? wk : wv;
    const int d0 = blockIdx.x * 32, e0 = blockIdx.y * 32;
    const int tx = threadIdx.x & 31, ty = threadIdx.x >> 5;
#pragma unroll
    for (int i = 0; i < 32; i += 8)
        t[ty + i][tx] = W[((size_t)h * DK_ + d0 + ty + i) * DH_ + e0 + tx];
    __syncthreads();
#pragma unroll
    for (int i = 0; i < 32; i += 8)
        g_Wt[((size_t)mh * DH_ + e0 + ty + i) * DK_ + d0 + tx] = cvt_tf32(t[tx][ty + i]);
}

// ---------------------------------------------------------------------------
// Projections with register prefetch across d-chunks.
// O[128 l x 64 e] = X[128 x 512] * W[512 x 64].  Q/K stored tf32, V raw.
// ---------------------------------------------------------------------------
__global__ __launch_bounds__(128) void proj_kernel(
    const float* __restrict__ q_in, const float* __restrict__ k_in,
    const float* __restrict__ v_in)
{
    extern __shared__ float sm[];
    float* Xs = sm;             // [128][STR]
    float* Ws = sm + 128*STR;   // [64][STR]

    const int mat = blockIdx.z, bh = blockIdx.y, l0 = blockIdx.x * 128;
    const int b = bh / H_, h = bh % H_;
    const float* X  = (mat == 0) ? q_in : (mat == 1) ? k_in : v_in;
    const float* Wt = g_Wt + ((size_t)(mat * H_ + h)) * DH_ * DK_;
    float*       O  = (mat == 0) ? g_Q : (mat == 1) ? g_K : g_V;

    const int tid = threadIdx.x, lane = tid & 31, wid = tid >> 5;
    const int wm = wid >> 1, wn = wid & 1;
    const int grp = lane >> 2, cp = lane & 3;
    const int xr = tid >> 4, xc = tid & 15;          // row/group for fills

    float4 xf[16], wf[8];
#pragma unroll
    for (int it = 0; it < 16; ++it)
        xf[it] = *(const float4*)(X + ((size_t)(b * L_ + l0 + xr + it*8)) * DK_ + xc * 4);
#pragma unroll
    for (int it = 0; it < 8; ++it)
        wf[it] = *(const float4*)(Wt + (size_t)(xr + it*8) * DK_ + xc * 4);

    float acc[4][4][4];
#pragma unroll
    for (int i = 0; i < 4; ++i)
#pragma unroll
        for (int j = 0; j < 4; ++j)
#pragma unroll
            for (int c = 0; c < 4; ++c) acc[i][j][c] = 0.f;

    for (int d0 = 0; d0 < DK_; d0 += 64) {
#pragma unroll
        for (int it = 0; it < 16; ++it)
            *(float4*)(Xs + (xr + it*8) * STR + xc * 4) = cvt4(xf[it]);
#pragma unroll
        for (int it = 0; it < 8; ++it)
            *(float4*)(Ws + (xr + it*8) * STR + xc * 4) = wf[it];   // Wt pre-rounded
        __syncthreads();
        if (d0 + 64 < DK_) {
#pragma unroll
            for (int it = 0; it < 16; ++it)
                xf[it] = *(const float4*)(X + ((size_t)(b * L_ + l0 + xr + it*8)) * DK_ + d0 + 64 + xc * 4);
#pragma unroll
            for (int it = 0; it < 8; ++it)
                wf[it] = *(const float4*)(Wt + (size_t)(xr + it*8) * DK_ + d0 + 64 + xc * 4);
        }
#pragma unroll
        for (int ks = 0; ks < 8; ++ks) {
            float a[4][4];
#pragma unroll
            for (int mt = 0; mt < 4; ++mt) {
                const float* base = Xs + (wm*64 + mt*16 + grp) * STR + ks*8 + cp;
                a[mt][0] = base[0];       a[mt][2] = base[4];
                a[mt][1] = base[8*STR];   a[mt][3] = base[8*STR + 4];
            }
            float bf[4][2];
#pragma unroll
            for (int nt = 0; nt < 4; ++nt) {
                const float* base = Ws + (wn*32 + nt*8 + grp) * STR + ks*8 + cp;
                bf[nt][0] = base[0];      bf[nt][1] = base[4];
            }
#pragma unroll
            for (int mt = 0; mt < 4; ++mt)
#pragma unroll
                for (int nt = 0; nt < 4; ++nt)
                    mma_tf32(acc[mt][nt], a[mt][0], a[mt][1], a[mt][2], a[mt][3],
                             bf[nt][0], bf[nt][1]);
        }
        __syncthreads();
    }
    const bool rnd = (mat < 2);  // Q,K rounded to tf32; V raw
#pragma unroll
    for (int mt = 0; mt < 4; ++mt) {
        int l = l0 + wm*64 + mt*16 + grp;
#pragma unroll
        for (int nt = 0; nt < 4; ++nt) {
            int e = wn*32 + nt*8 + cp*2;
            float2 v0 = make_float2(acc[mt][nt][0], acc[mt][nt][1]);
            float2 v1 = make_float2(acc[mt][nt][2], acc[mt][nt][3]);
            if (rnd) {
                v0 = make_float2(cvt_tf32(v0.x), cvt_tf32(v0.y));
                v1 = make_float2(cvt_tf32(v1.x), cvt_tf32(v1.y));
            }
            *(float2*)(O + ((size_t)bh*L_ + l)*DH_ + e)     = v0;
            *(float2*)(O + ((size_t)bh*L_ + l + 8)*DH_ + e) = v1;
        }
    }
}

// ---------------------------------------------------------------------------
// QK^T + exp + column partial sums.  Inputs pre-rounded; P stored streaming.
// ---------------------------------------------------------------------------
__global__ __launch_bounds__(256) void qk_kernel()
{
    extern __shared__ float sm[];
    float* Qs = sm;
    float* Ks = sm + 128*STR;
    float* Cs = sm + 2*128*STR;

    const int bh = blockIdx.z, qb = blockIdx.y, kb = blockIdx.x;
    const int q0 = qb * 128, k0 = kb * 128;
    const int tid = threadIdx.x, lane = tid & 31, wid = tid >> 5;
    const int wm = wid >> 2, wn = wid & 3;
    const int grp = lane >> 2, cp = lane & 3;
    const int xr = tid >> 4, xc = tid & 15;

#pragma unroll
    for (int it = 0; it < 8; ++it) {
        int r = xr + it*16;
        cp16(Qs + r*STR + xc*4, g_Q + ((size_t)bh*L_ + q0 + r)*DH_ + xc*4);
        cp16(Ks + r*STR + xc*4, g_K + ((size_t)bh*L_ + k0 + r)*DH_ + xc*4);
    }
    cp_commit();
    cp_wait<0>();
    __syncthreads();

    float acc[4][4][4];
#pragma unroll
    for (int i = 0; i < 4; ++i)
#pragma unroll
        for (int j = 0; j < 4; ++j)
#pragma unroll
            for (int c = 0; c < 4; ++c) acc[i][j][c] = 0.f;

#pragma unroll
    for (int ks = 0; ks < 8; ++ks) {
        float a[4][4];
#pragma unroll
        for (int mt = 0; mt < 4; ++mt) {
            const float* base = Qs + (wm*64 + mt*16 + grp) * STR + ks*8 + cp;
            a[mt][0] = base[0];      a[mt][2] = base[4];
            a[mt][1] = base[8*STR];  a[mt][3] = base[8*STR + 4];
        }
        float bf[4][2];
#pragma unroll
        for (int nt = 0; nt < 4; ++nt) {
            const float* base = Ks + (wn*32 + nt*8 + grp) * STR + ks*8 + cp;
            bf[nt][0] = base[0];     bf[nt][1] = base[4];
        }
#pragma unroll
        for (int mt = 0; mt < 4; ++mt)
#pragma unroll
            for (int nt = 0; nt < 4; ++nt)
                mma_tf32(acc[mt][nt], a[mt][0], a[mt][1], a[mt][2], a[mt][3],
                         bf[nt][0], bf[nt][1]);
    }

    const float rsc = 0.02209708691207961f;  // 1/sqrt(2048)
    float cs0[4] = {0,0,0,0}, cs1[4] = {0,0,0,0};
#pragma unroll
    for (int mt = 0; mt < 4; ++mt) {
        int q = q0 + wm*64 + mt*16 + grp;
#pragma unroll
        for (int nt = 0; nt < 4; ++nt) {
            int k = k0 + wn*32 + nt*8 + cp*2;
            float p0 = __expf(acc[mt][nt][0] * rsc);
            float p1 = __expf(acc[mt][nt][1] * rsc);
            float p2 = __expf(acc[mt][nt][2] * rsc);
            float p3 = __expf(acc[mt][nt][3] * rsc);
            cs0[nt] += p0 + p2;  cs1[nt] += p1 + p3;
            __stcs((float2*)(g_P + ((size_t)bh*L_ + q)*L_ + k),
                   make_float2(cvt_tf32(p0), cvt_tf32(p1)));
            __stcs((float2*)(g_P + ((size_t)bh*L_ + q + 8)*L_ + k),
                   make_float2(cvt_tf32(p2), cvt_tf32(p3)));
        }
    }
#pragma unroll
    for (int nt = 0; nt < 4; ++nt) {
        cs0[nt] += __shfl_xor_sync(0xffffffffu, cs0[nt], 4);
        cs0[nt] += __shfl_xor_sync(0xffffffffu, cs0[nt], 8);
        cs0[nt] += __shfl_xor_sync(0xffffffffu, cs0[nt], 16);
        cs1[nt] += __shfl_xor_sync(0xffffffffu, cs1[nt], 4);
        cs1[nt] += __shfl_xor_sync(0xffffffffu, cs1[nt], 8);
        cs1[nt] += __shfl_xor_sync(0xffffffffu, cs1[nt], 16);
    }
    if (lane < 4) {
#pragma unroll
        for (int nt = 0; nt < 4; ++nt) {
            Cs[wm*128 + wn*32 + nt*8 + lane*2]     = cs0[nt];
            Cs[wm*128 + wn*32 + nt*8 + lane*2 + 1] = cs1[nt];
        }
    }
    __syncthreads();
    if (tid < 128)
        g_Dp[((size_t)bh*QB_ + qb)*L_ + k0 + tid] = Cs[tid] + Cs[128 + tid];
}

// ---------------------------------------------------------------------------
__global__ __launch_bounds__(256) void dred_kernel()
{
    int g  = blockIdx.x * 256 + threadIdx.x;
    int bh = g / L_, k = g % L_;
    float s = 0.f;
#pragma unroll
    for (int qt = 0; qt < QB_; ++qt) s += g_Dp[((size_t)bh*QB_ + qt)*L_ + k];
    g_Dinv[g] = 1.0f / s;
}

// ---------------------------------------------------------------------------
__global__ __launch_bounds__(256) void vprep_kernel()
{
    __shared__ float t[32][33];
    const int bh = blockIdx.z;
    const int k0 = blockIdx.x * 32, e0 = blockIdx.y * 32;
    const int tx = threadIdx.x & 31, ty = threadIdx.x >> 5;
#pragma unroll
    for (int i = 0; i < 32; i += 8) {
        int k = k0 + ty + i;
        t[ty + i][tx] = g_V[((size_t)bh*L_ + k)*DH_ + e0 + tx] * g_Dinv[bh*L_ + k];
    }
    __syncthreads();
#pragma unroll
    for (int i = 0; i < 32; i += 8)
        g_Vt[((size_t)bh*DH_ + e0 + ty + i)*L_ + k0 + tx] = cvt_tf32(t[tx][ty + i]);
}

// ---------------------------------------------------------------------------
// PV with 2-stage cp.async pipeline.  out = P @ (V/D), k-chunks of 64.
// 128 threads, warps 2x2, warp tile 64x32.
// ---------------------------------------------------------------------------
__global__ __launch_bounds__(128, 2) void pv_kernel(float* __restrict__ out)
{
    extern __shared__ float sm[];
    // stage s: Ps = sm + s*192*STR, Vs = Ps + 128*STR
    const int bh = blockIdx.y, q0 = blockIdx.x * 128;
    const int b = bh / H_, h = bh % H_;
    const int tid = threadIdx.x, lane = tid & 31, wid = tid >> 5;
    const int wm = wid >> 1, wn = wid & 1;
    const int grp = lane >> 2, cp = lane & 3;
    const int xr = tid >> 4, xc = tid & 15;

    const float* Pbase = g_P + ((size_t)bh*L_ + q0)*L_;
    const float* Vbase = g_Vt + (size_t)bh*DH_*L_;

    // fill stage s with k-chunk k0
    auto fill = [&](int s, int k0) {
        float* Ps = sm + s*192*STR;
        float* Vs = Ps + 128*STR;
#pragma unroll
        for (int it = 0; it < 16; ++it) {
            int r = xr + it*8;
            cp16(Ps + r*STR + xc*4, Pbase + (size_t)r*L_ + k0 + xc*4);
        }
#pragma unroll
        for (int it = 0; it < 8; ++it) {
            int r = xr + it*8;
            cp16(Vs + r*STR + xc*4, Vbase + (size_t)r*L_ + k0 + xc*4);
        }
        cp_commit();
    };

    float acc[4][4][4];
#pragma unroll
    for (int i = 0; i < 4; ++i)
#pragma unroll
        for (int j = 0; j < 4; ++j)
#pragma unroll
            for (int c = 0; c < 4; ++c) acc[i][j][c] = 0.f;

    fill(0, 0);

    for (int it = 0; it < L_/64; ++it) {
        int s = it & 1;
        if (it + 1 < L_/64) { fill(1 - s, (it + 1) * 64); cp_wait<1>(); }
        else                { cp_wait<0>(); }
        __syncthreads();

        const float* Ps = sm + s*192*STR;
        const float* Vs = Ps + 128*STR;
#pragma unroll
        for (int ks = 0; ks < 8; ++ks) {
            float a[4][4];
#pragma unroll
            for (int mt = 0; mt < 4; ++mt) {
                const float* base = Ps + (wm*64 + mt*16 + grp) * STR + ks*8 + cp;
                a[mt][0] = base[0];      a[mt][2] = base[4];
                a[mt][1] = base[8*STR];  a[mt][3] = base[8*STR + 4];
            }
            float bf[4][2];
#pragma unroll
            for (int nt = 0; nt < 4; ++nt) {
                const float* base = Vs + (wn*32 + nt*8 + grp) * STR + ks*8 + cp;
                bf[nt][0] = base[0];     bf[nt][1] = base[4];
            }
#pragma unroll
            for (int mt = 0; mt < 4; ++mt)
#pragma unroll
                for (int nt = 0; nt < 4; ++nt)
                    mma_tf32(acc[mt][nt], a[mt][0], a[mt][1], a[mt][2], a[mt][3],
                             bf[nt][0], bf[nt][1]);
        }
        __syncthreads();
    }
#pragma unroll
    for (int mt = 0; mt < 4; ++mt) {
        int q = q0 + wm*64 + mt*16 + grp;
#pragma unroll
        for (int nt = 0; nt < 4; ++nt) {
            int e = wn*32 + nt*8 + cp*2;
            *(float2*)(out + ((size_t)b*L_ + q)*(H_*DH_) + h*DH_ + e) =
                make_float2(acc[mt][nt][0], acc[mt][nt][1]);
            *(float2*)(out + ((size_t)b*L_ + q + 8)*(H_*DH_) + h*DH_ + e) =
                make_float2(acc[mt][nt][2], acc[mt][nt][3]);
        }
    }
}

// ---------------------------------------------------------------------------
extern "C" void kernel_launch(void* const* d_in, const int* in_sizes, int n_in,
                              void* d_out, int out_size)
{
    const float* keys    = (const float*)d_in[0];
    const float* queries = (const float*)d_in[1];
    const float* values  = (const float*)d_in[2];
    const float* WQ      = (const float*)d_in[3];
    const float* WK      = (const float*)d_in[4];
    const float* WV      = (const float*)d_in[5];
    float* out = (float*)d_out;

    const int PP_SMEM = (192*STR) * 4;            // 52224
    const int QK_SMEM = (2*128*STR + 256) * 4;    // 70656
    const int PV_SMEM = (2*192*STR) * 4;          // 104448

    cudaFuncSetAttribute(proj_kernel, cudaFuncAttributeMaxDynamicSharedMemorySize, PP_SMEM);
    cudaFuncSetAttribute(qk_kernel,   cudaFuncAttributeMaxDynamicSharedMemorySize, QK_SMEM);
    cudaFuncSetAttribute(pv_kernel,   cudaFuncAttributeMaxDynamicSharedMemorySize, PV_SMEM);

    wprep_kernel<<<dim3(DK_/32, DH_/32, 24), 256>>>(WQ, WK, WV);
    proj_kernel<<<dim3(L_/128, BH_, 3), 128, PP_SMEM>>>(queries, keys, values);
    qk_kernel<<<dim3(L_/128, L_/128, BH_), 256, QK_SMEM>>>();
    dred_kernel<<<(BH_*L_)/256, 256>>>();
    vprep_kernel<<<dim3(L_/32, DH_/32, BH_), 256>>>();
    pv_kernel<<<dim3(L_/128, BH_), 128, PV_SMEM>>>(out);
}

// round 5
// speedup vs baseline: 1.6891x; 1.3263x over previous
#include <cuda_runtime.h>
#include <cuda_fp16.h>
#include <cstdint>

#define B_  2
#define L_  2048
#define DK_ 512
#define H_  8
#define DH_ 64
#define BH_ (B_*H_)
#define QB_ (L_/128)
#define STR 68          // fp32 smem stride (proj)
#define HSTR 72         // half smem stride for 64-wide tiles
#define PHSTR 136       // half smem stride for 128-wide tiles

// ---- device scratch ----
__device__ __align__(256) __half g_Qh[BH_*L_*DH_];
__device__ __align__(256) __half g_Kh[BH_*L_*DH_];
__device__ __align__(256) float  g_V[BH_*L_*DH_];
__device__ __align__(256) float  g_Wt[3*H_*DH_*DK_];       // tf32 [mat][h][e][d]
__device__ __align__(256) __half g_Vth[BH_*DH_*L_];        // [bh][e][k] = V*Dinv
__device__ __align__(256) __half g_Ph[(size_t)BH_*L_*L_];  // 128 MiB
__device__ __align__(256) float  g_Dp[BH_*QB_*L_];

__device__ __forceinline__ float cvt_tf32(float x) {
    uint32_t r; asm("cvt.rna.tf32.f32 %0, %1;" : "=r"(r) : "f"(x));
    return __uint_as_float(r);
}
__device__ __forceinline__ float4 cvt4(float4 v) {
    return make_float4(cvt_tf32(v.x), cvt_tf32(v.y), cvt_tf32(v.z), cvt_tf32(v.w));
}
__device__ __forceinline__ void mma_tf32(float* d, float a0, float a1, float a2, float a3,
                                         float b0, float b1) {
    asm volatile("mma.sync.aligned.m16n8k8.row.col.f32.tf32.tf32.f32 "
                 "{%0,%1,%2,%3}, {%4,%5,%6,%7}, {%8,%9}, {%0,%1,%2,%3};"
                 : "+f"(d[0]), "+f"(d[1]), "+f"(d[2]), "+f"(d[3])
                 : "r"(__float_as_uint(a0)), "r"(__float_as_uint(a1)),
                   "r"(__float_as_uint(a2)), "r"(__float_as_uint(a3)),
                   "r"(__float_as_uint(b0)), "r"(__float_as_uint(b1)));
}
__device__ __forceinline__ void mma_f16(float* d, uint32_t a0, uint32_t a1, uint32_t a2,
                                        uint32_t a3, uint32_t b0, uint32_t b1) {
    asm volatile("mma.sync.aligned.m16n8k16.row.col.f32.f16.f16.f32 "
                 "{%0,%1,%2,%3}, {%4,%5,%6,%7}, {%8,%9}, {%0,%1,%2,%3};"
                 : "+f"(d[0]), "+f"(d[1]), "+f"(d[2]), "+f"(d[3])
                 : "r"(a0), "r"(a1), "r"(a2), "r"(a3), "r"(b0), "r"(b1));
}
__device__ __forceinline__ void cp16(void* dst_smem, const void* src) {
    uint32_t d = (uint32_t)__cvta_generic_to_shared(dst_smem);
    asm volatile("cp.async.cg.shared.global [%0], [%1], 16;" :: "r"(d), "l"(src));
}
__device__ __forceinline__ void cp_commit() { asm volatile("cp.async.commit_group;"); }
template<int N> __device__ __forceinline__ void cp_wait() {
    asm volatile("cp.async.wait_group %0;" :: "n"(N));
}

// ---------------------------------------------------------------------------
__global__ __launch_bounds__(256) void wprep_kernel(
    const float* __restrict__ wq, const float* __restrict__ wk,
    const float* __restrict__ wv)
{
    __shared__ float t[32][33];
    const int mh  = blockIdx.z;
    const int mat = mh / H_, h = mh % H_;
    const float* W = (mat == 0) ? wq : (mat == 1) ? wk : wv;
    const int d0 = blockIdx.x * 32, e0 = blockIdx.y * 32;
    const int tx = threadIdx.x & 31, ty = threadIdx.x >> 5;
#pragma unroll
    for (int i = 0; i < 32; i += 8)
        t[ty + i][tx] = W[((size_t)h * DK_ + d0 + ty + i) * DH_ + e0 + tx];
    __syncthreads();
#pragma unroll
    for (int i = 0; i < 32; i += 8)
        g_Wt[((size_t)mh * DH_ + e0 + ty + i) * DK_ + d0 + tx] = cvt_tf32(t[tx][ty + i]);
}

// ---------------------------------------------------------------------------
// Projections (tf32 mma, register prefetch).  Q,K stored half; V stored fp32.
// ---------------------------------------------------------------------------
__global__ __launch_bounds__(128) void proj_kernel(
    const float* __restrict__ q_in, const float* __restrict__ k_in,
    const float* __restrict__ v_in)
{
    extern __shared__ float sm[];
    float* Xs = sm;             // [128][STR]
    float* Ws = sm + 128*STR;   // [64][STR]

    const int mat = blockIdx.z, bh = blockIdx.y, l0 = blockIdx.x * 128;
    const int b = bh / H_, h = bh % H_;
    const float* X  = (mat == 0) ? q_in : (mat == 1) ? k_in : v_in;
    const float* Wt = g_Wt + ((size_t)(mat * H_ + h)) * DH_ * DK_;

    const int tid = threadIdx.x, lane = tid & 31, wid = tid >> 5;
    const int wm = wid >> 1, wn = wid & 1;
    const int grp = lane >> 2, cp = lane & 3;
    const int xr = tid >> 4, xc = tid & 15;

    float4 xf[16], wf[8];
#pragma unroll
    for (int it = 0; it < 16; ++it)
        xf[it] = *(const float4*)(X + ((size_t)(b * L_ + l0 + xr + it*8)) * DK_ + xc * 4);
#pragma unroll
    for (int it = 0; it < 8; ++it)
        wf[it] = *(const float4*)(Wt + (size_t)(xr + it*8) * DK_ + xc * 4);

    float acc[4][4][4];
#pragma unroll
    for (int i = 0; i < 4; ++i)
#pragma unroll
        for (int j = 0; j < 4; ++j)
#pragma unroll
            for (int c = 0; c < 4; ++c) acc[i][j][c] = 0.f;

    for (int d0 = 0; d0 < DK_; d0 += 64) {
#pragma unroll
        for (int it = 0; it < 16; ++it)
            *(float4*)(Xs + (xr + it*8) * STR + xc * 4) = cvt4(xf[it]);
#pragma unroll
        for (int it = 0; it < 8; ++it)
            *(float4*)(Ws + (xr + it*8) * STR + xc * 4) = wf[it];
        __syncthreads();
        if (d0 + 64 < DK_) {
#pragma unroll
            for (int it = 0; it < 16; ++it)
                xf[it] = *(const float4*)(X + ((size_t)(b * L_ + l0 + xr + it*8)) * DK_ + d0 + 64 + xc * 4);
#pragma unroll
            for (int it = 0; it < 8; ++it)
                wf[it] = *(const float4*)(Wt + (size_t)(xr + it*8) * DK_ + d0 + 64 + xc * 4);
        }
#pragma unroll
        for (int ks = 0; ks < 8; ++ks) {
            float a[4][4];
#pragma unroll
            for (int mt = 0; mt < 4; ++mt) {
                const float* base = Xs + (wm*64 + mt*16 + grp) * STR + ks*8 + cp;
                a[mt][0] = base[0];       a[mt][2] = base[4];
                a[mt][1] = base[8*STR];   a[mt][3] = base[8*STR + 4];
            }
            float bf[4][2];
#pragma unroll
            for (int nt = 0; nt < 4; ++nt) {
                const float* base = Ws + (wn*32 + nt*8 + grp) * STR + ks*8 + cp;
                bf[nt][0] = base[0];      bf[nt][1] = base[4];
            }
#pragma unroll
            for (int mt = 0; mt < 4; ++mt)
#pragma unroll
                for (int nt = 0; nt < 4; ++nt)
                    mma_tf32(acc[mt][nt], a[mt][0], a[mt][1], a[mt][2], a[mt][3],
                             bf[nt][0], bf[nt][1]);
        }
        __syncthreads();
    }
#pragma unroll
    for (int mt = 0; mt < 4; ++mt) {
        int l = l0 + wm*64 + mt*16 + grp;
#pragma unroll
        for (int nt = 0; nt < 4; ++nt) {
            int e = wn*32 + nt*8 + cp*2;
            if (mat < 2) {
                __half* O = (mat == 0) ? g_Qh : g_Kh;
                *(__half2*)(O + ((size_t)bh*L_ + l)*DH_ + e) =
                    __floats2half2_rn(acc[mt][nt][0], acc[mt][nt][1]);
                *(__half2*)(O + ((size_t)bh*L_ + l + 8)*DH_ + e) =
                    __floats2half2_rn(acc[mt][nt][2], acc[mt][nt][3]);
            } else {
                *(float2*)(g_V + ((size_t)bh*L_ + l)*DH_ + e) =
                    make_float2(acc[mt][nt][0], acc[mt][nt][1]);
                *(float2*)(g_V + ((size_t)bh*L_ + l + 8)*DH_ + e) =
                    make_float2(acc[mt][nt][2], acc[mt][nt][3]);
            }
        }
    }
}

// ---------------------------------------------------------------------------
// QK^T (fp16 mma, fp32 accum) + exp + column partial sums. P stored half.
// Block 128q x 128k, 256 threads, warps 2x4, warp tile 64x32.
// ---------------------------------------------------------------------------
__global__ __launch_bounds__(256) void qk_kernel()
{
    extern __shared__ char smc[];
    __half* Qs = (__half*)smc;              // [128][HSTR]
    __half* Ks = Qs + 128*HSTR;             // [128][HSTR]
    float*  Cs = (float*)(Ks + 128*HSTR);   // [2][128]

    const int bh = blockIdx.z, qb = blockIdx.y, kb = blockIdx.x;
    const int q0 = qb * 128, k0 = kb * 128;
    const int tid = threadIdx.x, lane = tid & 31, wid = tid >> 5;
    const int wm = wid >> 2, wn = wid & 3;
    const int grp = lane >> 2, cp = lane & 3;

#pragma unroll
    for (int it = 0; it < 4; ++it) {
        int f = it * 256 + tid;
        int r = f >> 3, c8 = f & 7;
        cp16(Qs + r*HSTR + c8*8, g_Qh + ((size_t)bh*L_ + q0 + r)*DH_ + c8*8);
        cp16(Ks + r*HSTR + c8*8, g_Kh + ((size_t)bh*L_ + k0 + r)*DH_ + c8*8);
    }
    cp_commit();
    cp_wait<0>();
    __syncthreads();

    float acc[4][4][4];
#pragma unroll
    for (int i = 0; i < 4; ++i)
#pragma unroll
        for (int j = 0; j < 4; ++j)
#pragma unroll
            for (int c = 0; c < 4; ++c) acc[i][j][c] = 0.f;

#pragma unroll
    for (int ks = 0; ks < 4; ++ks) {
        uint32_t a[4][4];
#pragma unroll
        for (int mt = 0; mt < 4; ++mt) {
            const __half* base = Qs + (wm*64 + mt*16 + grp) * HSTR + ks*16 + cp*2;
            a[mt][0] = *(const uint32_t*)(base);
            a[mt][1] = *(const uint32_t*)(base + 8*HSTR);
            a[mt][2] = *(const uint32_t*)(base + 8);
            a[mt][3] = *(const uint32_t*)(base + 8*HSTR + 8);
        }
        uint32_t bf[4][2];
#pragma unroll
        for (int nt = 0; nt < 4; ++nt) {
            const __half* base = Ks + (wn*32 + nt*8 + grp) * HSTR + ks*16 + cp*2;
            bf[nt][0] = *(const uint32_t*)(base);
            bf[nt][1] = *(const uint32_t*)(base + 8);
        }
#pragma unroll
        for (int mt = 0; mt < 4; ++mt)
#pragma unroll
            for (int nt = 0; nt < 4; ++nt)
                mma_f16(acc[mt][nt], a[mt][0], a[mt][1], a[mt][2], a[mt][3],
                        bf[nt][0], bf[nt][1]);
    }

    const float rsc = 0.02209708691207961f;  // 1/sqrt(2048)
    float cs0[4] = {0,0,0,0}, cs1[4] = {0,0,0,0};
#pragma unroll
    for (int mt = 0; mt < 4; ++mt) {
        int q = q0 + wm*64 + mt*16 + grp;
#pragma unroll
        for (int nt = 0; nt < 4; ++nt) {
            int k = k0 + wn*32 + nt*8 + cp*2;
            float p0 = __expf(acc[mt][nt][0] * rsc);
            float p1 = __expf(acc[mt][nt][1] * rsc);
            float p2 = __expf(acc[mt][nt][2] * rsc);
            float p3 = __expf(acc[mt][nt][3] * rsc);
            cs0[nt] += p0 + p2;  cs1[nt] += p1 + p3;
            __stcs((__half2*)(g_Ph + ((size_t)bh*L_ + q)*L_ + k), __floats2half2_rn(p0, p1));
            __stcs((__half2*)(g_Ph + ((size_t)bh*L_ + q + 8)*L_ + k), __floats2half2_rn(p2, p3));
        }
    }
#pragma unroll
    for (int nt = 0; nt < 4; ++nt) {
        cs0[nt] += __shfl_xor_sync(0xffffffffu, cs0[nt], 4);
        cs0[nt] += __shfl_xor_sync(0xffffffffu, cs0[nt], 8);
        cs0[nt] += __shfl_xor_sync(0xffffffffu, cs0[nt], 16);
        cs1[nt] += __shfl_xor_sync(0xffffffffu, cs1[nt], 4);
        cs1[nt] += __shfl_xor_sync(0xffffffffu, cs1[nt], 8);
        cs1[nt] += __shfl_xor_sync(0xffffffffu, cs1[nt], 16);
    }
    if (lane < 4) {
#pragma unroll
        for (int nt = 0; nt < 4; ++nt) {
            Cs[wm*128 + wn*32 + nt*8 + lane*2]     = cs0[nt];
            Cs[wm*128 + wn*32 + nt*8 + lane*2 + 1] = cs1[nt];
        }
    }
    __syncthreads();
    if (tid < 128)
        g_Dp[((size_t)bh*QB_ + qb)*L_ + k0 + tid] = Cs[tid] + Cs[128 + tid];
}

// ---------------------------------------------------------------------------
// Vt prep (folds the D reduction): g_Vth[bh][e][k] = V[k][e] / D[k]
// ---------------------------------------------------------------------------
__global__ __launch_bounds__(256) void vprep_kernel()
{
    __shared__ float t[32][33];
    __shared__ float dv[32];
    const int bh = blockIdx.z;
    const int k0 = blockIdx.x * 32, e0 = blockIdx.y * 32;
    const int tx = threadIdx.x & 31, ty = threadIdx.x >> 5;
    if (threadIdx.x < 32) {
        float s = 0.f;
#pragma unroll
        for (int qt = 0; qt < QB_; ++qt)
            s += g_Dp[((size_t)bh*QB_ + qt)*L_ + k0 + threadIdx.x];
        dv[threadIdx.x] = 1.0f / s;
    }
    __syncthreads();
#pragma unroll
    for (int i = 0; i < 32; i += 8) {
        int k = k0 + ty + i;
        t[ty + i][tx] = g_V[((size_t)bh*L_ + k)*DH_ + e0 + tx] * dv[ty + i];
    }
    __syncthreads();
#pragma unroll
    for (int i = 0; i < 32; i += 8)
        g_Vth[((size_t)bh*DH_ + e0 + ty + i)*L_ + k0 + tx] = __float2half_rn(t[tx][ty + i]);
}

// ---------------------------------------------------------------------------
// PV (fp16 mma): out[256q x 64e] = P @ Vt^T, k-chunks of 128, 2-stage cp.async.
// 256 threads, warps 4x2, warp tile 64q x 32e.
// ---------------------------------------------------------------------------
__global__ __launch_bounds__(256, 1) void pv_kernel(float* __restrict__ out)
{
    extern __shared__ char smc[];
    const int STAGE = (256 + 64) * PHSTR;   // halfs per stage
    const int bh = blockIdx.y, q0 = blockIdx.x * 256;
    const int b = bh / H_, h = bh % H_;
    const int tid = threadIdx.x, lane = tid & 31, wid = tid >> 5;
    const int wm = wid >> 1, wn = wid & 1;
    const int grp = lane >> 2, cp = lane & 3;
    const int xr = tid >> 4, xc = tid & 15;

    const __half* Pbase = g_Ph + ((size_t)bh*L_ + q0)*L_;
    const __half* Vbase = g_Vth + (size_t)bh*DH_*L_;

    auto fill = [&](int s, int k0) {
        __half* Ps = (__half*)smc + s*STAGE;
        __half* Vs = Ps + 256*PHSTR;
#pragma unroll
        for (int it = 0; it < 16; ++it) {
            int r = xr + it*16;
            cp16(Ps + r*PHSTR + xc*8, Pbase + (size_t)r*L_ + k0 + xc*8);
        }
#pragma unroll
        for (int it = 0; it < 4; ++it) {
            int r = xr + it*16;
            cp16(Vs + r*PHSTR + xc*8, Vbase + (size_t)r*L_ + k0 + xc*8);
        }
        cp_commit();
    };

    float acc[4][4][4];
#pragma unroll
    for (int i = 0; i < 4; ++i)
#pragma unroll
        for (int j = 0; j < 4; ++j)
#pragma unroll
            for (int c = 0; c < 4; ++c) acc[i][j][c] = 0.f;

    fill(0, 0);

    for (int it = 0; it < L_/128; ++it) {
        int s = it & 1;
        if (it + 1 < L_/128) { fill(1 - s, (it + 1) * 128); cp_wait<1>(); }
        else                 { cp_wait<0>(); }
        __syncthreads();

        const __half* Ps = (__half*)smc + s*STAGE;
        const __half* Vs = Ps + 256*PHSTR;
#pragma unroll
        for (int ks = 0; ks < 8; ++ks) {
            uint32_t a[4][4];
#pragma unroll
            for (int mt = 0; mt < 4; ++mt) {
                const __half* base = Ps + (wm*64 + mt*16 + grp) * PHSTR + ks*16 + cp*2;
                a[mt][0] = *(const uint32_t*)(base);
                a[mt][1] = *(const uint32_t*)(base + 8*PHSTR);
                a[mt][2] = *(const uint32_t*)(base + 8);
                a[mt][3] = *(const uint32_t*)(base + 8*PHSTR + 8);
            }
            uint32_t bf[4][2];
#pragma unroll
            for (int nt = 0; nt < 4; ++nt) {
                const __half* base = Vs + (wn*32 + nt*8 + grp) * PHSTR + ks*16 + cp*2;
                bf[nt][0] = *(const uint32_t*)(base);
                bf[nt][1] = *(const uint32_t*)(base + 8);
            }
#pragma unroll
            for (int mt = 0; mt < 4; ++mt)
#pragma unroll
                for (int nt = 0; nt < 4; ++nt)
                    mma_f16(acc[mt][nt], a[mt][0], a[mt][1], a[mt][2], a[mt][3],
                            bf[nt][0], bf[nt][1]);
        }
        __syncthreads();
    }
#pragma unroll
    for (int mt = 0; mt < 4; ++mt) {
        int q = q0 + wm*64 + mt*16 + grp;
#pragma unroll
        for (int nt = 0; nt < 4; ++nt) {
            int e = wn*32 + nt*8 + cp*2;
            *(float2*)(out + ((size_t)b*L_ + q)*(H_*DH_) + h*DH_ + e) =
                make_float2(acc[mt][nt][0], acc[mt][nt][1]);
            *(float2*)(out + ((size_t)b*L_ + q + 8)*(H_*DH_) + h*DH_ + e) =
                make_float2(acc[mt][nt][2], acc[mt][nt][3]);
        }
    }
}

// ---------------------------------------------------------------------------
extern "C" void kernel_launch(void* const* d_in, const int* in_sizes, int n_in,
                              void* d_out, int out_size)
{
    const float* keys    = (const float*)d_in[0];
    const float* queries = (const float*)d_in[1];
    const float* values  = (const float*)d_in[2];
    const float* WQ      = (const float*)d_in[3];
    const float* WK      = (const float*)d_in[4];
    const float* WV      = (const float*)d_in[5];
    float* out = (float*)d_out;

    const int PP_SMEM = (192*STR) * 4;                 // 52224
    const int QK_SMEM = 2*128*HSTR*2 + 256*4;          // 37888
    const int PV_SMEM = 2*(256 + 64)*PHSTR*2;          // 174080

    cudaFuncSetAttribute(proj_kernel, cudaFuncAttributeMaxDynamicSharedMemorySize, PP_SMEM);
    cudaFuncSetAttribute(qk_kernel,   cudaFuncAttributeMaxDynamicSharedMemorySize, QK_SMEM);
    cudaFuncSetAttribute(pv_kernel,   cudaFuncAttributeMaxDynamicSharedMemorySize, PV_SMEM);

    wprep_kernel<<<dim3(DK_/32, DH_/32, 24), 256>>>(WQ, WK, WV);
    proj_kernel<<<dim3(L_/128, BH_, 3), 128, PP_SMEM>>>(queries, keys, values);
    qk_kernel<<<dim3(L_/128, L_/128, BH_), 256, QK_SMEM>>>();
    vprep_kernel<<<dim3(L_/32, DH_/32, BH_), 256>>>();
    pv_kernel<<<dim3(L_/256, BH_), 256, PV_SMEM>>>(out);
}

// round 7
// speedup vs baseline: 1.7067x; 1.0104x over previous
#include <cuda_runtime.h>
#include <cuda_fp16.h>
#include <cstdint>

#define B_  2
#define L_  2048
#define DK_ 512
#define H_  8
#define DH_ 64
#define BH_ (B_*H_)
#define QB_ (L_/128)
#define STR 68          // fp32 smem stride (proj)
#define HSTR 72         // half smem stride for 64-wide tiles  (144 B)
#define PHSTR 136       // half smem stride for 128-wide tiles (272 B)

// ---- device scratch ----
__device__ __align__(256) __half g_Qh[BH_*L_*DH_];
__device__ __align__(256) __half g_Kh[BH_*L_*DH_];
__device__ __align__(256) float  g_V[BH_*L_*DH_];
__device__ __align__(256) float  g_Wt[3*H_*DH_*DK_];       // tf32 [mat][h][e][d]
__device__ __align__(256) __half g_Vth[BH_*DH_*L_];        // [bh][e][k] = V*Dinv
__device__ __align__(256) __half g_Ph[(size_t)BH_*L_*L_];  // 128 MiB
__device__ __align__(256) float  g_Dp[BH_*QB_*L_];

__device__ __forceinline__ float cvt_tf32(float x) {
    uint32_t r; asm("cvt.rna.tf32.f32 %0, %1;" : "=r"(r) : "f"(x));
    return __uint_as_float(r);
}
__device__ __forceinline__ float4 cvt4(float4 v) {
    return make_float4(cvt_tf32(v.x), cvt_tf32(v.y), cvt_tf32(v.z), cvt_tf32(v.w));
}
__device__ __forceinline__ void mma_tf32(float* d, float a0, float a1, float a2, float a3,
                                         float b0, float b1) {
    asm volatile("mma.sync.aligned.m16n8k8.row.col.f32.tf32.tf32.f32 "
                 "{%0,%1,%2,%3}, {%4,%5,%6,%7}, {%8,%9}, {%0,%1,%2,%3};"
                 : "+f"(d[0]), "+f"(d[1]), "+f"(d[2]), "+f"(d[3])
                 : "r"(__float_as_uint(a0)), "r"(__float_as_uint(a1)),
                   "r"(__float_as_uint(a2)), "r"(__float_as_uint(a3)),
                   "r"(__float_as_uint(b0)), "r"(__float_as_uint(b1)));
}
__device__ __forceinline__ void mma_f16(float* d, uint32_t a0, uint32_t a1, uint32_t a2,
                                        uint32_t a3, uint32_t b0, uint32_t b1) {
    asm volatile("mma.sync.aligned.m16n8k16.row.col.f32.f16.f16.f32 "
                 "{%0,%1,%2,%3}, {%4,%5,%6,%7}, {%8,%9}, {%0,%1,%2,%3};"
                 : "+f"(d[0]), "+f"(d[1]), "+f"(d[2]), "+f"(d[3])
                 : "r"(a0), "r"(a1), "r"(a2), "r"(a3), "r"(b0), "r"(b1));
}
__device__ __forceinline__ void ldm_x4(uint32_t* r, uint32_t saddr) {
    asm volatile("ldmatrix.sync.aligned.m8n8.x4.shared.b16 {%0,%1,%2,%3}, [%4];"
                 : "=r"(r[0]), "=r"(r[1]), "=r"(r[2]), "=r"(r[3]) : "r"(saddr));
}
__device__ __forceinline__ void cp16(void* dst_smem, const void* src) {
    uint32_t d = (uint32_t)__cvta_generic_to_shared(dst_smem);
    asm volatile("cp.async.cg.shared.global [%0], [%1], 16;" :: "r"(d), "l"(src));
}
__device__ __forceinline__ void cp_commit() { asm volatile("cp.async.commit_group;"); }
template<int N> __device__ __forceinline__ void cp_wait() {
    asm volatile("cp.async.wait_group %0;" :: "n"(N));
}

// ---------------------------------------------------------------------------
__global__ __launch_bounds__(256) void wprep_kernel(
    const float* __restrict__ wq, const float* __restrict__ wk,
    const float* __restrict__ wv)
{
    __shared__ float t[32][33];
    const int mh  = blockIdx.z;
    const int mat = mh / H_, h = mh % H_;
    const float* W = (mat == 0) ? wq : (mat == 1) ? wk : wv;
    const int d0 = blockIdx.x * 32, e0 = blockIdx.y * 32;
    const int tx = threadIdx.x & 31, ty = threadIdx.x >> 5;
#pragma unroll
    for (int i = 0; i < 32; i += 8)
        t[ty + i][tx] = W[((size_t)h * DK_ + d0 + ty + i) * DH_ + e0 + tx];
    __syncthreads();
#pragma unroll
    for (int i = 0; i < 32; i += 8)
        g_Wt[((size_t)mh * DH_ + e0 + ty + i) * DK_ + d0 + tx] = cvt_tf32(t[tx][ty + i]);
}

// ---------------------------------------------------------------------------
// Projections (tf32 mma, register prefetch).  Q,K stored half; V stored fp32.
// ---------------------------------------------------------------------------
__global__ __launch_bounds__(128) void proj_kernel(
    const float* __restrict__ q_in, const float* __restrict__ k_in,
    const float* __restrict__ v_in)
{
    extern __shared__ float sm[];
    float* Xs = sm;             // [128][STR]
    float* Ws = sm + 128*STR;   // [64][STR]

    const int mat = blockIdx.z, bh = blockIdx.y, l0 = blockIdx.x * 128;
    const int b = bh / H_, h = bh % H_;
    const float* X  = (mat == 0) ? q_in : (mat == 1) ? k_in : v_in;
    const float* Wt = g_Wt + ((size_t)(mat * H_ + h)) * DH_ * DK_;

    const int tid = threadIdx.x, lane = tid & 31, wid = tid >> 5;
    const int wm = wid >> 1, wn = wid & 1;
    const int grp = lane >> 2, cp = lane & 3;
    const int xr = tid >> 4, xc = tid & 15;

    float4 xf[16], wf[8];
#pragma unroll
    for (int it = 0; it < 16; ++it)
        xf[it] = *(const float4*)(X + ((size_t)(b * L_ + l0 + xr + it*8)) * DK_ + xc * 4);
#pragma unroll
    for (int it = 0; it < 8; ++it)
        wf[it] = *(const float4*)(Wt + (size_t)(xr + it*8) * DK_ + xc * 4);

    float acc[4][4][4];
#pragma unroll
    for (int i = 0; i < 4; ++i)
#pragma unroll
        for (int j = 0; j < 4; ++j)
#pragma unroll
            for (int c = 0; c < 4; ++c) acc[i][j][c] = 0.f;

    for (int d0 = 0; d0 < DK_; d0 += 64) {
#pragma unroll
        for (int it = 0; it < 16; ++it)
            *(float4*)(Xs + (xr + it*8) * STR + xc * 4) = cvt4(xf[it]);
#pragma unroll
        for (int it = 0; it < 8; ++it)
            *(float4*)(Ws + (xr + it*8) * STR + xc * 4) = wf[it];
        __syncthreads();
        if (d0 + 64 < DK_) {
#pragma unroll
            for (int it = 0; it < 16; ++it)
                xf[it] = *(const float4*)(X + ((size_t)(b * L_ + l0 + xr + it*8)) * DK_ + d0 + 64 + xc * 4);
#pragma unroll
            for (int it = 0; it < 8; ++it)
                wf[it] = *(const float4*)(Wt + (size_t)(xr + it*8) * DK_ + d0 + 64 + xc * 4);
        }
#pragma unroll
        for (int ks = 0; ks < 8; ++ks) {
            float a[4][4];
#pragma unroll
            for (int mt = 0; mt < 4; ++mt) {
                const float* base = Xs + (wm*64 + mt*16 + grp) * STR + ks*8 + cp;
                a[mt][0] = base[0];       a[mt][2] = base[4];
                a[mt][1] = base[8*STR];   a[mt][3] = base[8*STR + 4];
            }
            float bf[4][2];
#pragma unroll
            for (int nt = 0; nt < 4; ++nt) {
                const float* base = Ws + (wn*32 + nt*8 + grp) * STR + ks*8 + cp;
                bf[nt][0] = base[0];      bf[nt][1] = base[4];
            }
#pragma unroll
            for (int mt = 0; mt < 4; ++mt)
#pragma unroll
                for (int nt = 0; nt < 4; ++nt)
                    mma_tf32(acc[mt][nt], a[mt][0], a[mt][1], a[mt][2], a[mt][3],
                             bf[nt][0], bf[nt][1]);
        }
        __syncthreads();
    }
#pragma unroll
    for (int mt = 0; mt < 4; ++mt) {
        int l = l0 + wm*64 + mt*16 + grp;
#pragma unroll
        for (int nt = 0; nt < 4; ++nt) {
            int e = wn*32 + nt*8 + cp*2;
            if (mat < 2) {
                __half* O = (mat == 0) ? g_Qh : g_Kh;
                *(__half2*)(O + ((size_t)bh*L_ + l)*DH_ + e) =
                    __floats2half2_rn(acc[mt][nt][0], acc[mt][nt][1]);
                *(__half2*)(O + ((size_t)bh*L_ + l + 8)*DH_ + e) =
                    __floats2half2_rn(acc[mt][nt][2], acc[mt][nt][3]);
            } else {
                *(float2*)(g_V + ((size_t)bh*L_ + l)*DH_ + e) =
                    make_float2(acc[mt][nt][0], acc[mt][nt][1]);
                *(float2*)(g_V + ((size_t)bh*L_ + l + 8)*DH_ + e) =
                    make_float2(acc[mt][nt][2], acc[mt][nt][3]);
            }
        }
    }
}

// ---------------------------------------------------------------------------
// QK^T (fp16 mma + ldmatrix) + exp + column partial sums. P stored half.
// Block 128q x 128k, 256 threads, warps 2x4, warp tile 64x32.
// ---------------------------------------------------------------------------
__global__ __launch_bounds__(256) void qk_kernel()
{
    extern __shared__ char smc[];
    __half* Qs = (__half*)smc;              // [128][HSTR]
    __half* Ks = Qs + 128*HSTR;             // [128][HSTR]
    float*  Cs = (float*)(Ks + 128*HSTR);   // [2][128]

    const int bh = blockIdx.z, qb = blockIdx.y, kb = blockIdx.x;
    const int q0 = qb * 128, k0 = kb * 128;
    const int tid = threadIdx.x, lane = tid & 31, wid = tid >> 5;
    const int wm = wid >> 2, wn = wid & 3;
    const int grp = lane >> 2, cp = lane & 3;

#pragma unroll
    for (int it = 0; it < 4; ++it) {
        int f = it * 256 + tid;
        int r = f >> 3, c8 = f & 7;
        cp16(Qs + r*HSTR + c8*8, g_Qh + ((size_t)bh*L_ + q0 + r)*DH_ + c8*8);
        cp16(Ks + r*HSTR + c8*8, g_Kh + ((size_t)bh*L_ + k0 + r)*DH_ + c8*8);
    }
    cp_commit();
    cp_wait<0>();
    __syncthreads();

    // ldmatrix lane addressing
    const uint32_t Qs_u = (uint32_t)__cvta_generic_to_shared(Qs);
    const uint32_t Ks_u = (uint32_t)__cvta_generic_to_shared(Ks);
    const uint32_t a_base = Qs_u + (uint32_t)(wm*64 + (lane & 15)) * (HSTR*2) + (lane >> 4) * 16;
    const uint32_t b_base = Ks_u + (uint32_t)(wn*32 + ((lane >> 4) & 1)*8 + (lane & 7)) * (HSTR*2)
                                 + ((lane >> 3) & 1) * 16;

    float acc[4][4][4];
#pragma unroll
    for (int i = 0; i < 4; ++i)
#pragma unroll
        for (int j = 0; j < 4; ++j)
#pragma unroll
            for (int c = 0; c < 4; ++c) acc[i][j][c] = 0.f;

#pragma unroll
    for (int ks = 0; ks < 4; ++ks) {
        uint32_t a[4][4], bf[4][2];
#pragma unroll
        for (int mt = 0; mt < 4; ++mt)
            ldm_x4(a[mt], a_base + mt*16*(HSTR*2) + ks*32);
#pragma unroll
        for (int np = 0; np < 2; ++np) {
            uint32_t bt[4];
            ldm_x4(bt, b_base + np*16*(HSTR*2) + ks*32);
            bf[2*np][0] = bt[0];   bf[2*np][1] = bt[1];
            bf[2*np+1][0] = bt[2]; bf[2*np+1][1] = bt[3];
        }
#pragma unroll
        for (int mt = 0; mt < 4; ++mt)
#pragma unroll
            for (int nt = 0; nt < 4; ++nt)
                mma_f16(acc[mt][nt], a[mt][0], a[mt][1], a[mt][2], a[mt][3],
                        bf[nt][0], bf[nt][1]);
    }

    const float rsc = 0.02209708691207961f;  // 1/sqrt(2048)
    float cs0[4] = {0,0,0,0}, cs1[4] = {0,0,0,0};
#pragma unroll
    for (int mt = 0; mt < 4; ++mt) {
        int q = q0 + wm*64 + mt*16 + grp;
#pragma unroll
        for (int nt = 0; nt < 4; ++nt) {
            int k = k0 + wn*32 + nt*8 + cp*2;
            float p0 = __expf(acc[mt][nt][0] * rsc);
            float p1 = __expf(acc[mt][nt][1] * rsc);
            float p2 = __expf(acc[mt][nt][2] * rsc);
            float p3 = __expf(acc[mt][nt][3] * rsc);
            cs0[nt] += p0 + p2;  cs1[nt] += p1 + p3;
            __stcs((__half2*)(g_Ph + ((size_t)bh*L_ + q)*L_ + k), __floats2half2_rn(p0, p1));
            __stcs((__half2*)(g_Ph + ((size_t)bh*L_ + q + 8)*L_ + k), __floats2half2_rn(p2, p3));
        }
    }
#pragma unroll
    for (int nt = 0; nt < 4; ++nt) {
        cs0[nt] += __shfl_xor_sync(0xffffffffu, cs0[nt], 4);
        cs0[nt] += __shfl_xor_sync(0xffffffffu, cs0[nt], 8);
        cs0[nt] += __shfl_xor_sync(0xffffffffu, cs0[nt], 16);
        cs1[nt] += __shfl_xor_sync(0xffffffffu, cs1[nt], 4);
        cs1[nt] += __shfl_xor_sync(0xffffffffu, cs1[nt], 8);
        cs1[nt] += __shfl_xor_sync(0xffffffffu, cs1[nt], 16);
    }
    if (lane < 4) {
#pragma unroll
        for (int nt = 0; nt < 4; ++nt) {
            Cs[wm*128 + wn*32 + nt*8 + lane*2]     = cs0[nt];
            Cs[wm*128 + wn*32 + nt*8 + lane*2 + 1] = cs1[nt];
        }
    }
    __syncthreads();
    if (tid < 128)
        g_Dp[((size_t)bh*QB_ + qb)*L_ + k0 + tid] = Cs[tid] + Cs[128 + tid];
}

// ---------------------------------------------------------------------------
// Vt prep (folds D reduction): g_Vth[bh][e][k] = V[k][e] / D[k]
// ---------------------------------------------------------------------------
__global__ __launch_bounds__(256) void vprep_kernel()
{
    __shared__ float t[32][33];
    __shared__ float dv[32];
    const int bh = blockIdx.z;
    const int k0 = blockIdx.x * 32, e0 = blockIdx.y * 32;
    const int tx = threadIdx.x & 31, ty = threadIdx.x >> 5;
    if (threadIdx.x < 32) {
        float s = 0.f;
#pragma unroll
        for (int qt = 0; qt < QB_; ++qt)
            s += g_Dp[((size_t)bh*QB_ + qt)*L_ + k0 + threadIdx.x];
        dv[threadIdx.x] = 1.0f / s;
    }
    __syncthreads();
#pragma unroll
    for (int i = 0; i < 32; i += 8) {
        int k = k0 + ty + i;
        t[ty + i][tx] = g_V[((size_t)bh*L_ + k)*DH_ + e0 + tx] * dv[ty + i];
    }
    __syncthreads();
#pragma unroll
    for (int i = 0; i < 32; i += 8)
        g_Vth[((size_t)bh*DH_ + e0 + ty + i)*L_ + k0 + tx] = __float2half_rn(t[tx][ty + i]);
}

// ---------------------------------------------------------------------------
// PV (fp16 mma + ldmatrix): out[256q x 64e] = P @ Vt^T, k-chunks of 128,
// 2-stage cp.async.  256 threads, warps 4x2, warp tile 64q x 32e.
// ---------------------------------------------------------------------------
__global__ __launch_bounds__(256, 1) void pv_kernel(float* __restrict__ out)
{
    extern __shared__ char smc[];
    const int STAGE = (256 + 64) * PHSTR;   // halfs per stage
    const int bh = blockIdx.y, q0 = blockIdx.x * 256;
    const int b = bh / H_, h = bh % H_;
    const int tid = threadIdx.x, lane = tid & 31, wid = tid >> 5;
    const int wm = wid >> 1, wn = wid & 1;
    const int grp = lane >> 2, cp = lane & 3;
    const int xr = tid >> 4, xc = tid & 15;

    const __half* Pbase = g_Ph + ((size_t)bh*L_ + q0)*L_;
    const __half* Vbase = g_Vth + (size_t)bh*DH_*L_;

    auto fill = [&](int s, int k0) {
        __half* Ps = (__half*)smc + s*STAGE;
        __half* Vs = Ps + 256*PHSTR;
#pragma unroll
        for (int it = 0; it < 16; ++it) {
            int r = xr + it*16;
            cp16(Ps + r*PHSTR + xc*8, Pbase + (size_t)r*L_ + k0 + xc*8);
        }
#pragma unroll
        for (int it = 0; it < 4; ++it) {
            int r = xr + it*16;
            cp16(Vs + r*PHSTR + xc*8, Vbase + (size_t)r*L_ + k0 + xc*8);
        }
        cp_commit();
    };

    float acc[4][4][4];
#pragma unroll
    for (int i = 0; i < 4; ++i)
#pragma unroll
        for (int j = 0; j < 4; ++j)
#pragma unroll
            for (int c = 0; c < 4; ++c) acc[i][j][c] = 0.f;

    fill(0, 0);

    const uint32_t a_lrow = (uint32_t)(wm*64 + (lane & 15));
    const uint32_t a_csel = (uint32_t)(lane >> 4) * 16;
    const uint32_t b_lrow = (uint32_t)(wn*32 + ((lane >> 4) & 1)*8 + (lane & 7));
    const uint32_t b_csel = (uint32_t)((lane >> 3) & 1) * 16;

    for (int it = 0; it < L_/128; ++it) {
        int s = it & 1;
        if (it + 1 < L_/128) { fill(1 - s, (it + 1) * 128); cp_wait<1>(); }
        else                 { cp_wait<0>(); }
        __syncthreads();

        const __half* Ps = (__half*)smc + s*STAGE;
        const __half* Vs = Ps + 256*PHSTR;
        const uint32_t Ps_u = (uint32_t)__cvta_generic_to_shared(Ps);
        const uint32_t Vs_u = (uint32_t)__cvta_generic_to_shared(Vs);
        const uint32_t a_base = Ps_u + a_lrow * (PHSTR*2) + a_csel;
        const uint32_t b_base = Vs_u + b_lrow * (PHSTR*2) + b_csel;

#pragma unroll
        for (int ks = 0; ks < 8; ++ks) {
            uint32_t a[4][4], bf[4][2];
#pragma unroll
            for (int mt = 0; mt < 4; ++mt)
                ldm_x4(a[mt], a_base + mt*16*(PHSTR*2) + ks*32);
#pragma unroll
            for (int np = 0; np < 2; ++np) {
                uint32_t bt[4];
                ldm_x4(bt, b_base + np*16*(PHSTR*2) + ks*32);
                bf[2*np][0] = bt[0];   bf[2*np][1] = bt[1];
                bf[2*np+1][0] = bt[2]; bf[2*np+1][1] = bt[3];
            }
#pragma unroll
            for (int mt = 0; mt < 4; ++mt)
#pragma unroll
                for (int nt = 0; nt < 4; ++nt)
                    mma_f16(acc[mt][nt], a[mt][0], a[mt][1], a[mt][2], a[mt][3],
                            bf[nt][0], bf[nt][1]);
        }
        __syncthreads();
    }
#pragma unroll
    for (int mt = 0; mt < 4; ++mt) {
        int q = q0 + wm*64 + mt*16 + grp;
#pragma unroll
        for (int nt = 0; nt < 4; ++nt) {
            int e = wn*32 + nt*8 + cp*2;
            *(float2*)(out + ((size_t)b*L_ + q)*(H_*DH_) + h*DH_ + e) =
                make_float2(acc[mt][nt][0], acc[mt][nt][1]);
            *(float2*)(out + ((size_t)b*L_ + q + 8)*(H_*DH_) + h*DH_ + e) =
                make_float2(acc[mt][nt][2], acc[mt][nt][3]);
        }
    }
}

// ---------------------------------------------------------------------------
extern "C" void kernel_launch(void* const* d_in, const int* in_sizes, int n_in,
                              void* d_out, int out_size)
{
    const float* keys    = (const float*)d_in[0];
    const float* queries = (const float*)d_in[1];
    const float* values  = (const float*)d_in[2];
    const float* WQ      = (const float*)d_in[3];
    const float* WK      = (const float*)d_in[4];
    const float* WV      = (const float*)d_in[5];
    float* out = (float*)d_out;

    const int PP_SMEM = (192*STR) * 4;                 // 52224
    const int QK_SMEM = 2*128*HSTR*2 + 256*4;          // 37888
    const int PV_SMEM = 2*(256 + 64)*PHSTR*2;          // 174080

    cudaFuncSetAttribute(proj_kernel, cudaFuncAttributeMaxDynamicSharedMemorySize, PP_SMEM);
    cudaFuncSetAttribute(qk_kernel,   cudaFuncAttributeMaxDynamicSharedMemorySize, QK_SMEM);
    cudaFuncSetAttribute(pv_kernel,   cudaFuncAttributeMaxDynamicSharedMemorySize, PV_SMEM);

    wprep_kernel<<<dim3(DK_/32, DH_/32, 24), 256>>>(WQ, WK, WV);
    proj_kernel<<<dim3(L_/128, BH_, 3), 128, PP_SMEM>>>(queries, keys, values);
    qk_kernel<<<dim3(L_/128, L_/128, BH_), 256, QK_SMEM>>>();
    vprep_kernel<<<dim3(L_/32, DH_/32, BH_), 256>>>();
    pv_kernel<<<dim3(L_/256, BH_), 256, PV_SMEM>>>(out);
}

// round 8
// speedup vs baseline: 1.8000x; 1.0546x over previous
#include <cuda_runtime.h>
#include <cuda_fp16.h>
#include <cstdint>

#define B_  2
#define L_  2048
#define DK_ 512
#define H_  8
#define DH_ 64
#define BH_ (B_*H_)
#define QB_ (L_/128)
#define STR 68          // fp32 smem stride (proj)
#define HSTR 72         // half smem stride for 64-wide tiles  (144 B)
#define PHSTR 136       // half smem stride for 128-wide tiles (272 B)

// ---- device scratch ----
__device__ __align__(256) __half g_Qh[BH_*L_*DH_];
__device__ __align__(256) __half g_Kh[BH_*L_*DH_];
__device__ __align__(256) float  g_V[BH_*L_*DH_];
__device__ __align__(256) __half g_Vth[BH_*DH_*L_];        // [bh][e][k] = V*Dinv
__device__ __align__(256) __half g_Ph[(size_t)BH_*L_*L_];  // 128 MiB
__device__ __align__(256) float  g_Dp[BH_*QB_*L_];

__device__ __forceinline__ float cvt_tf32(float x) {
    uint32_t r; asm("cvt.rna.tf32.f32 %0, %1;" : "=r"(r) : "f"(x));
    return __uint_as_float(r);
}
__device__ __forceinline__ float4 cvt4(float4 v) {
    return make_float4(cvt_tf32(v.x), cvt_tf32(v.y), cvt_tf32(v.z), cvt_tf32(v.w));
}
__device__ __forceinline__ float ex2(float x) {
    float r; asm("ex2.approx.f32 %0, %1;" : "=f"(r) : "f"(x));
    return r;
}
__device__ __forceinline__ void mma_tf32(float* d, float a0, float a1, float a2, float a3,
                                         float b0, float b1) {
    asm volatile("mma.sync.aligned.m16n8k8.row.col.f32.tf32.tf32.f32 "
                 "{%0,%1,%2,%3}, {%4,%5,%6,%7}, {%8,%9}, {%0,%1,%2,%3};"
                 : "+f"(d[0]), "+f"(d[1]), "+f"(d[2]), "+f"(d[3])
                 : "r"(__float_as_uint(a0)), "r"(__float_as_uint(a1)),
                   "r"(__float_as_uint(a2)), "r"(__float_as_uint(a3)),
                   "r"(__float_as_uint(b0)), "r"(__float_as_uint(b1)));
}
__device__ __forceinline__ void mma_f16(float* d, uint32_t a0, uint32_t a1, uint32_t a2,
                                        uint32_t a3, uint32_t b0, uint32_t b1) {
    asm volatile("mma.sync.aligned.m16n8k16.row.col.f32.f16.f16.f32 "
                 "{%0,%1,%2,%3}, {%4,%5,%6,%7}, {%8,%9}, {%0,%1,%2,%3};"
                 : "+f"(d[0]), "+f"(d[1]), "+f"(d[2]), "+f"(d[3])
                 : "r"(a0), "r"(a1), "r"(a2), "r"(a3), "r"(b0), "r"(b1));
}
__device__ __forceinline__ void ldm_x4(uint32_t* r, uint32_t saddr) {
    asm volatile("ldmatrix.sync.aligned.m8n8.x4.shared.b16 {%0,%1,%2,%3}, [%4];"
                 : "=r"(r[0]), "=r"(r[1]), "=r"(r[2]), "=r"(r[3]) : "r"(saddr));
}
__device__ __forceinline__ void cp16(void* dst_smem, const void* src) {
    uint32_t d = (uint32_t)__cvta_generic_to_shared(dst_smem);
    asm volatile("cp.async.cg.shared.global [%0], [%1], 16;" :: "r"(d), "l"(src));
}
__device__ __forceinline__ void cp_commit() { asm volatile("cp.async.commit_group;"); }
template<int N> __device__ __forceinline__ void cp_wait() {
    asm volatile("cp.async.wait_group %0;" :: "n"(N));
}

// ---------------------------------------------------------------------------
// Projections (tf32 mma, register prefetch).  W loaded directly ([d][e] tiles).
// Q,K stored half; V stored fp32.
// ---------------------------------------------------------------------------
__global__ __launch_bounds__(128) void proj_kernel(
    const float* __restrict__ q_in, const float* __restrict__ k_in,
    const float* __restrict__ v_in, const float* __restrict__ wq,
    const float* __restrict__ wk,  const float* __restrict__ wv)
{
    extern __shared__ float sm[];
    float* Xs = sm;             // [128 rows l][STR]  (k-major)
    float* Ws = sm + 128*STR;   // [64 rows d][STR]   (e-major rows: natural W)

    const int mat = blockIdx.z, bh = blockIdx.y, l0 = blockIdx.x * 128;
    const int b = bh / H_, h = bh % H_;
    const float* X = (mat == 0) ? q_in : (mat == 1) ? k_in : v_in;
    const float* W = ((mat == 0) ? wq : (mat == 1) ? wk : wv) + (size_t)h * DK_ * DH_;

    const int tid = threadIdx.x, lane = tid & 31, wid = tid >> 5;
    const int wm = wid >> 1, wn = wid & 1;
    const int grp = lane >> 2, cp = lane & 3;
    const int xr = tid >> 4, xc = tid & 15;

    float4 xf[16], wf[8];
#pragma unroll
    for (int it = 0; it < 16; ++it)
        xf[it] = *(const float4*)(X + ((size_t)(b * L_ + l0 + xr + it*8)) * DK_ + xc * 4);
#pragma unroll
    for (int it = 0; it < 8; ++it)
        wf[it] = *(const float4*)(W + (size_t)(xr + it*8) * DH_ + xc * 4);

    float acc[4][4][4];
#pragma unroll
    for (int i = 0; i < 4; ++i)
#pragma unroll
        for (int j = 0; j < 4; ++j)
#pragma unroll
            for (int c = 0; c < 4; ++c) acc[i][j][c] = 0.f;

    for (int d0 = 0; d0 < DK_; d0 += 64) {
#pragma unroll
        for (int it = 0; it < 16; ++it)
            *(float4*)(Xs + (xr + it*8) * STR + xc * 4) = cvt4(xf[it]);
#pragma unroll
        for (int it = 0; it < 8; ++it)
            *(float4*)(Ws + (xr + it*8) * STR + xc * 4) = cvt4(wf[it]);
        __syncthreads();
        if (d0 + 64 < DK_) {
#pragma unroll
            for (int it = 0; it < 16; ++it)
                xf[it] = *(const float4*)(X + ((size_t)(b * L_ + l0 + xr + it*8)) * DK_ + d0 + 64 + xc * 4);
#pragma unroll
            for (int it = 0; it < 8; ++it)
                wf[it] = *(const float4*)(W + (size_t)(d0 + 64 + xr + it*8) * DH_ + xc * 4);
        }
#pragma unroll
        for (int ks = 0; ks < 8; ++ks) {
            float a[4][4];
#pragma unroll
            for (int mt = 0; mt < 4; ++mt) {
                const float* base = Xs + (wm*64 + mt*16 + grp) * STR + ks*8 + cp;
                a[mt][0] = base[0];       a[mt][2] = base[4];
                a[mt][1] = base[8*STR];   a[mt][3] = base[8*STR + 4];
            }
            float bf[4][2];
#pragma unroll
            for (int nt = 0; nt < 4; ++nt) {
                // B fragment from natural W[d][e]: row = k (d), col = e
                const float* base = Ws + (ks*8 + cp) * STR + wn*32 + nt*8 + grp;
                bf[nt][0] = base[0];      bf[nt][1] = base[4*STR];
            }
#pragma unroll
            for (int mt = 0; mt < 4; ++mt)
#pragma unroll
                for (int nt = 0; nt < 4; ++nt)
                    mma_tf32(acc[mt][nt], a[mt][0], a[mt][1], a[mt][2], a[mt][3],
                             bf[nt][0], bf[nt][1]);
        }
        __syncthreads();
    }
#pragma unroll
    for (int mt = 0; mt < 4; ++mt) {
        int l = l0 + wm*64 + mt*16 + grp;
#pragma unroll
        for (int nt = 0; nt < 4; ++nt) {
            int e = wn*32 + nt*8 + cp*2;
            if (mat < 2) {
                __half* O = (mat == 0) ? g_Qh : g_Kh;
                *(__half2*)(O + ((size_t)bh*L_ + l)*DH_ + e) =
                    __floats2half2_rn(acc[mt][nt][0], acc[mt][nt][1]);
                *(__half2*)(O + ((size_t)bh*L_ + l + 8)*DH_ + e) =
                    __floats2half2_rn(acc[mt][nt][2], acc[mt][nt][3]);
            } else {
                *(float2*)(g_V + ((size_t)bh*L_ + l)*DH_ + e) =
                    make_float2(acc[mt][nt][0], acc[mt][nt][1]);
                *(float2*)(g_V + ((size_t)bh*L_ + l + 8)*DH_ + e) =
                    make_float2(acc[mt][nt][2], acc[mt][nt][3]);
            }
        }
    }
}

// ---------------------------------------------------------------------------
// QK^T (fp16 mma + ldmatrix) + exp2 + column partial sums. P stored half.
// Block 128q x 256k, 256 threads, warps 2x4, warp tile 64x32, two k-halves.
// ---------------------------------------------------------------------------
__global__ __launch_bounds__(256) void qk_kernel()
{
    extern __shared__ char smc[];
    __half* Qs = (__half*)smc;              // [128][HSTR]
    __half* Ks = Qs + 128*HSTR;             // [256][HSTR]
    float*  Cs = (float*)(Ks + 256*HSTR);   // [2][128]

    const int bh = blockIdx.z, qb = blockIdx.y, kb = blockIdx.x;
    const int q0 = qb * 128, k0 = kb * 256;
    const int tid = threadIdx.x, lane = tid & 31, wid = tid >> 5;
    const int wm = wid >> 2, wn = wid & 3;
    const int grp = lane >> 2, cp = lane & 3;

#pragma unroll
    for (int it = 0; it < 4; ++it) {
        int f = it * 256 + tid;
        int r = f >> 3, c8 = f & 7;
        cp16(Qs + r*HSTR + c8*8, g_Qh + ((size_t)bh*L_ + q0 + r)*DH_ + c8*8);
    }
#pragma unroll
    for (int it = 0; it < 8; ++it) {
        int f = it * 256 + tid;
        int r = f >> 3, c8 = f & 7;
        cp16(Ks + r*HSTR + c8*8, g_Kh + ((size_t)bh*L_ + k0 + r)*DH_ + c8*8);
    }
    cp_commit();
    cp_wait<0>();
    __syncthreads();

    const uint32_t Qs_u = (uint32_t)__cvta_generic_to_shared(Qs);
    const uint32_t Ks_u = (uint32_t)__cvta_generic_to_shared(Ks);
    const uint32_t a_base = Qs_u + (uint32_t)(wm*64 + (lane & 15)) * (HSTR*2) + (lane >> 4) * 16;
    const uint32_t b_base0 = Ks_u + (uint32_t)(wn*32 + ((lane >> 4) & 1)*8 + (lane & 7)) * (HSTR*2)
                                  + ((lane >> 3) & 1) * 16;

    const float rsc2 = 0.03188117935f;  // log2(e)/sqrt(2048)

#pragma unroll
    for (int kb2 = 0; kb2 < 2; ++kb2) {
        float acc[4][4][4];
#pragma unroll
        for (int i = 0; i < 4; ++i)
#pragma unroll
            for (int j = 0; j < 4; ++j)
#pragma unroll
                for (int c = 0; c < 4; ++c) acc[i][j][c] = 0.f;

        const uint32_t b_base = b_base0 + (uint32_t)kb2 * 128 * (HSTR*2);
#pragma unroll
        for (int ks = 0; ks < 4; ++ks) {
            uint32_t a[4][4], bf[4][2];
#pragma unroll
            for (int mt = 0; mt < 4; ++mt)
                ldm_x4(a[mt], a_base + mt*16*(HSTR*2) + ks*32);
#pragma unroll
            for (int np = 0; np < 2; ++np) {
                uint32_t bt[4];
                ldm_x4(bt, b_base + np*16*(HSTR*2) + ks*32);
                bf[2*np][0] = bt[0];   bf[2*np][1] = bt[1];
                bf[2*np+1][0] = bt[2]; bf[2*np+1][1] = bt[3];
            }
#pragma unroll
            for (int mt = 0; mt < 4; ++mt)
#pragma unroll
                for (int nt = 0; nt < 4; ++nt)
                    mma_f16(acc[mt][nt], a[mt][0], a[mt][1], a[mt][2], a[mt][3],
                            bf[nt][0], bf[nt][1]);
        }

        float cs0[4] = {0,0,0,0}, cs1[4] = {0,0,0,0};
#pragma unroll
        for (int mt = 0; mt < 4; ++mt) {
            int q = q0 + wm*64 + mt*16 + grp;
#pragma unroll
            for (int nt = 0; nt < 4; ++nt) {
                int k = k0 + kb2*128 + wn*32 + nt*8 + cp*2;
                float p0 = ex2(acc[mt][nt][0] * rsc2);
                float p1 = ex2(acc[mt][nt][1] * rsc2);
                float p2 = ex2(acc[mt][nt][2] * rsc2);
                float p3 = ex2(acc[mt][nt][3] * rsc2);
                cs0[nt] += p0 + p2;  cs1[nt] += p1 + p3;
                __stcs((__half2*)(g_Ph + ((size_t)bh*L_ + q)*L_ + k), __floats2half2_rn(p0, p1));
                __stcs((__half2*)(g_Ph + ((size_t)bh*L_ + q + 8)*L_ + k), __floats2half2_rn(p2, p3));
            }
        }
#pragma unroll
        for (int nt = 0; nt < 4; ++nt) {
            cs0[nt] += __shfl_xor_sync(0xffffffffu, cs0[nt], 4);
            cs0[nt] += __shfl_xor_sync(0xffffffffu, cs0[nt], 8);
            cs0[nt] += __shfl_xor_sync(0xffffffffu, cs0[nt], 16);
            cs1[nt] += __shfl_xor_sync(0xffffffffu, cs1[nt], 4);
            cs1[nt] += __shfl_xor_sync(0xffffffffu, cs1[nt], 8);
            cs1[nt] += __shfl_xor_sync(0xffffffffu, cs1[nt], 16);
        }
        if (lane < 4) {
#pragma unroll
            for (int nt = 0; nt < 4; ++nt) {
                Cs[wm*128 + wn*32 + nt*8 + lane*2]     = cs0[nt];
                Cs[wm*128 + wn*32 + nt*8 + lane*2 + 1] = cs1[nt];
            }
        }
        __syncthreads();
        if (tid < 128)
            g_Dp[((size_t)bh*QB_ + qb)*L_ + k0 + kb2*128 + tid] = Cs[tid] + Cs[128 + tid];
        __syncthreads();
    }
}

// ---------------------------------------------------------------------------
// Vt prep (folds D reduction): g_Vth[bh][e][k] = V[k][e] / D[k]
// ---------------------------------------------------------------------------
__global__ __launch_bounds__(256) void vprep_kernel()
{
    __shared__ float t[32][33];
    __shared__ float dv[32];
    const int bh = blockIdx.z;
    const int k0 = blockIdx.x * 32, e0 = blockIdx.y * 32;
    const int tx = threadIdx.x & 31, ty = threadIdx.x >> 5;
    if (threadIdx.x < 32) {
        float s = 0.f;
#pragma unroll
        for (int qt = 0; qt < QB_; ++qt)
            s += g_Dp[((size_t)bh*QB_ + qt)*L_ + k0 + threadIdx.x];
        dv[threadIdx.x] = 1.0f / s;
    }
    __syncthreads();
#pragma unroll
    for (int i = 0; i < 32; i += 8) {
        int k = k0 + ty + i;
        t[ty + i][tx] = g_V[((size_t)bh*L_ + k)*DH_ + e0 + tx] * dv[ty + i];
    }
    __syncthreads();
#pragma unroll
    for (int i = 0; i < 32; i += 8)
        g_Vth[((size_t)bh*DH_ + e0 + ty + i)*L_ + k0 + tx] = __float2half_rn(t[tx][ty + i]);
}

// ---------------------------------------------------------------------------
// PV (fp16 mma + ldmatrix): out[256q x 64e] = P @ Vt^T, k-chunks of 128,
// 2-stage cp.async.  256 threads, warps 4x2, warp tile 64q x 32e.
// ---------------------------------------------------------------------------
__global__ __launch_bounds__(256, 1) void pv_kernel(float* __restrict__ out)
{
    extern __shared__ char smc[];
    const int STAGE = (256 + 64) * PHSTR;   // halfs per stage
    const int bh = blockIdx.y, q0 = blockIdx.x * 256;
    const int b = bh / H_, h = bh % H_;
    const int tid = threadIdx.x, lane = tid & 31, wid = tid >> 5;
    const int wm = wid >> 1, wn = wid & 1;
    const int grp = lane >> 2, cp = lane & 3;
    const int xr = tid >> 4, xc = tid & 15;

    const __half* Pbase = g_Ph + ((size_t)bh*L_ + q0)*L_;
    const __half* Vbase = g_Vth + (size_t)bh*DH_*L_;

    auto fill = [&](int s, int k0) {
        __half* Ps = (__half*)smc + s*STAGE;
        __half* Vs = Ps + 256*PHSTR;
#pragma unroll
        for (int it = 0; it < 16; ++it) {
            int r = xr + it*16;
            cp16(Ps + r*PHSTR + xc*8, Pbase + (size_t)r*L_ + k0 + xc*8);
        }
#pragma unroll
        for (int it = 0; it < 4; ++it) {
            int r = xr + it*16;
            cp16(Vs + r*PHSTR + xc*8, Vbase + (size_t)r*L_ + k0 + xc*8);
        }
        cp_commit();
    };

    float acc[4][4][4];
#pragma unroll
    for (int i = 0; i < 4; ++i)
#pragma unroll
        for (int j = 0; j < 4; ++j)
#pragma unroll
            for (int c = 0; c < 4; ++c) acc[i][j][c] = 0.f;

    fill(0, 0);

    const uint32_t a_lrow = (uint32_t)(wm*64 + (lane & 15));
    const uint32_t a_csel = (uint32_t)(lane >> 4) * 16;
    const uint32_t b_lrow = (uint32_t)(wn*32 + ((lane >> 4) & 1)*8 + (lane & 7));
    const uint32_t b_csel = (uint32_t)((lane >> 3) & 1) * 16;

    for (int it = 0; it < L_/128; ++it) {
        int s = it & 1;
        if (it + 1 < L_/128) { fill(1 - s, (it + 1) * 128); cp_wait<1>(); }
        else                 { cp_wait<0>(); }
        __syncthreads();

        const __half* Ps = (__half*)smc + s*STAGE;
        const __half* Vs = Ps + 256*PHSTR;
        const uint32_t Ps_u = (uint32_t)__cvta_generic_to_shared(Ps);
        const uint32_t Vs_u = (uint32_t)__cvta_generic_to_shared(Vs);
        const uint32_t a_base = Ps_u + a_lrow * (PHSTR*2) + a_csel;
        const uint32_t b_base = Vs_u + b_lrow * (PHSTR*2) + b_csel;

#pragma unroll
        for (int ks = 0; ks < 8; ++ks) {
            uint32_t a[4][4], bf[4][2];
#pragma unroll
            for (int mt = 0; mt < 4; ++mt)
                ldm_x4(a[mt], a_base + mt*16*(PHSTR*2) + ks*32);
#pragma unroll
            for (int np = 0; np < 2; ++np) {
                uint32_t bt[4];
                ldm_x4(bt, b_base + np*16*(PHSTR*2) + ks*32);
                bf[2*np][0] = bt[0];   bf[2*np][1] = bt[1];
                bf[2*np+1][0] = bt[2]; bf[2*np+1][1] = bt[3];
            }
#pragma unroll
            for (int mt = 0; mt < 4; ++mt)
#pragma unroll
                for (int nt = 0; nt < 4; ++nt)
                    mma_f16(acc[mt][nt], a[mt][0], a[mt][1], a[mt][2], a[mt][3],
                            bf[nt][0], bf[nt][1]);
        }
        __syncthreads();
    }
#pragma unroll
    for (int mt = 0; mt < 4; ++mt) {
        int q = q0 + wm*64 + mt*16 + grp;
#pragma unroll
        for (int nt = 0; nt < 4; ++nt) {
            int e = wn*32 + nt*8 + cp*2;
            *(float2*)(out + ((size_t)b*L_ + q)*(H_*DH_) + h*DH_ + e) =
                make_float2(acc[mt][nt][0], acc[mt][nt][1]);
            *(float2*)(out + ((size_t)b*L_ + q + 8)*(H_*DH_) + h*DH_ + e) =
                make_float2(acc[mt][nt][2], acc[mt][nt][3]);
        }
    }
}

// ---------------------------------------------------------------------------
extern "C" void kernel_launch(void* const* d_in, const int* in_sizes, int n_in,
                              void* d_out, int out_size)
{
    const float* keys    = (const float*)d_in[0];
    const float* queries = (const float*)d_in[1];
    const float* values  = (const float*)d_in[2];
    const float* WQ      = (const float*)d_in[3];
    const float* WK      = (const float*)d_in[4];
    const float* WV      = (const float*)d_in[5];
    float* out = (float*)d_out;

    const int PP_SMEM = (192*STR) * 4;                 // 52224
    const int QK_SMEM = (128 + 256)*HSTR*2 + 256*4;    // 56320
    const int PV_SMEM = 2*(256 + 64)*PHSTR*2;          // 174080

    cudaFuncSetAttribute(proj_kernel, cudaFuncAttributeMaxDynamicSharedMemorySize, PP_SMEM);
    cudaFuncSetAttribute(qk_kernel,   cudaFuncAttributeMaxDynamicSharedMemorySize, QK_SMEM);
    cudaFuncSetAttribute(pv_kernel,   cudaFuncAttributeMaxDynamicSharedMemorySize, PV_SMEM);

    proj_kernel<<<dim3(L_/128, BH_, 3), 128, PP_SMEM>>>(queries, keys, values, WQ, WK, WV);
    qk_kernel<<<dim3(L_/256, L_/128, BH_), 256, QK_SMEM>>>();
    vprep_kernel<<<dim3(L_/32, DH_/32, BH_), 256>>>();
    pv_kernel<<<dim3(L_/256, BH_), 256, PV_SMEM>>>(out);
}

// round 9
// speedup vs baseline: 2.0743x; 1.1524x over previous
#include <cuda_runtime.h>
#include <cuda_fp16.h>
#include <cstdint>

#define B_  2
#define L_  2048
#define DK_ 512
#define H_  8
#define DH_ 64
#define BH_ (B_*H_)
#define QB_ (L_/128)
#define STR 68          // fp32 smem stride (vproj)
#define HSTR 72         // half smem stride for 64-wide tiles  (144 B)
#define PHSTR 136       // half smem stride for 128-wide tiles (272 B)

// ---- device scratch ----
__device__ __align__(256) __half g_Qh[BH_*L_*DH_];
__device__ __align__(256) __half g_Kh[BH_*L_*DH_];
__device__ __align__(256) float  g_V[BH_*L_*DH_];
__device__ __align__(256) __half g_Vth[BH_*DH_*L_];        // [bh][e][k] = V*Dinv
__device__ __align__(256) __half g_Ph[(size_t)BH_*L_*L_];  // 128 MiB
__device__ __align__(256) float  g_Dp[BH_*QB_*L_];

__device__ __forceinline__ float cvt_tf32(float x) {
    uint32_t r; asm("cvt.rna.tf32.f32 %0, %1;" : "=r"(r) : "f"(x));
    return __uint_as_float(r);
}
__device__ __forceinline__ float4 cvt4(float4 v) {
    return make_float4(cvt_tf32(v.x), cvt_tf32(v.y), cvt_tf32(v.z), cvt_tf32(v.w));
}
__device__ __forceinline__ float ex2(float x) {
    float r; asm("ex2.approx.f32 %0, %1;" : "=f"(r) : "f"(x));
    return r;
}
__device__ __forceinline__ void mma_tf32(float* d, float a0, float a1, float a2, float a3,
                                         float b0, float b1) {
    asm volatile("mma.sync.aligned.m16n8k8.row.col.f32.tf32.tf32.f32 "
                 "{%0,%1,%2,%3}, {%4,%5,%6,%7}, {%8,%9}, {%0,%1,%2,%3};"
                 : "+f"(d[0]), "+f"(d[1]), "+f"(d[2]), "+f"(d[3])
                 : "r"(__float_as_uint(a0)), "r"(__float_as_uint(a1)),
                   "r"(__float_as_uint(a2)), "r"(__float_as_uint(a3)),
                   "r"(__float_as_uint(b0)), "r"(__float_as_uint(b1)));
}
__device__ __forceinline__ void mma_f16(float* d, uint32_t a0, uint32_t a1, uint32_t a2,
                                        uint32_t a3, uint32_t b0, uint32_t b1) {
    asm volatile("mma.sync.aligned.m16n8k16.row.col.f32.f16.f16.f32 "
                 "{%0,%1,%2,%3}, {%4,%5,%6,%7}, {%8,%9}, {%0,%1,%2,%3};"
                 : "+f"(d[0]), "+f"(d[1]), "+f"(d[2]), "+f"(d[3])
                 : "r"(a0), "r"(a1), "r"(a2), "r"(a3), "r"(b0), "r"(b1));
}
__device__ __forceinline__ void ldm_x4(uint32_t* r, uint32_t saddr) {
    asm volatile("ldmatrix.sync.aligned.m8n8.x4.shared.b16 {%0,%1,%2,%3}, [%4];"
                 : "=r"(r[0]), "=r"(r[1]), "=r"(r[2]), "=r"(r[3]) : "r"(saddr));
}
__device__ __forceinline__ void ldm_x4t(uint32_t* r, uint32_t saddr) {
    asm volatile("ldmatrix.sync.aligned.m8n8.x4.trans.shared.b16 {%0,%1,%2,%3}, [%4];"
                 : "=r"(r[0]), "=r"(r[1]), "=r"(r[2]), "=r"(r[3]) : "r"(saddr));
}
__device__ __forceinline__ void cp16(void* dst_smem, const void* src) {
    uint32_t d = (uint32_t)__cvta_generic_to_shared(dst_smem);
    asm volatile("cp.async.cg.shared.global [%0], [%1], 16;" :: "r"(d), "l"(src));
}
__device__ __forceinline__ void cp_commit() { asm volatile("cp.async.commit_group;"); }
template<int N> __device__ __forceinline__ void cp_wait() {
    asm volatile("cp.async.wait_group %0;" :: "n"(N));
}
// 4x4 u32 transpose across a lane quad (lanes differing in bits 0-1).
__device__ __forceinline__ void quad_tr(uint32_t x[4], int cp) {
    uint32_t s0 = (cp & 2) ? x[0] : x[2];
    uint32_t s1 = (cp & 2) ? x[1] : x[3];
    uint32_t r0 = __shfl_xor_sync(0xffffffffu, s0, 2);
    uint32_t r1 = __shfl_xor_sync(0xffffffffu, s1, 2);
    if (cp & 2) { x[0] = r0; x[1] = r1; } else { x[2] = r0; x[3] = r1; }
    uint32_t s2 = (cp & 1) ? x[0] : x[1];
    uint32_t s3 = (cp & 1) ? x[2] : x[3];
    uint32_t r2 = __shfl_xor_sync(0xffffffffu, s2, 1);
    uint32_t r3 = __shfl_xor_sync(0xffffffffu, s3, 1);
    if (cp & 1) { x[0] = r2; x[2] = r3; } else { x[1] = r2; x[3] = r3; }
}

// ---------------------------------------------------------------------------
// Q/K projections in fp16 mma.  A = X[128l x 64d] (fp16), B = W[d][e] via
// ldmatrix.trans.  128 threads, warps 2x2, warp tile 64l x 32e.
// ---------------------------------------------------------------------------
__global__ __launch_bounds__(128) void qkproj_kernel(
    const float* __restrict__ q_in, const float* __restrict__ k_in,
    const float* __restrict__ wq,  const float* __restrict__ wk)
{
    extern __shared__ char smc[];
    __half* Xs = (__half*)smc;       // [128][HSTR]
    __half* Ws = Xs + 128*HSTR;      // [64][HSTR]  (natural W rows: d-major)

    const int mat = blockIdx.z, bh = blockIdx.y, l0 = blockIdx.x * 128;
    const int b = bh / H_, h = bh % H_;
    const float* X = mat ? k_in : q_in;
    const float* W = (mat ? wk : wq) + (size_t)h * DK_ * DH_;
    __half* O = mat ? g_Kh : g_Qh;

    const int tid = threadIdx.x, lane = tid & 31, wid = tid >> 5;
    const int wm = wid >> 1, wn = wid & 1;
    const int grp = lane >> 2, cp = lane & 3;
    const int xr = tid >> 4, xc = tid & 15;

    float4 xf[16], wf[8];
#pragma unroll
    for (int it = 0; it < 16; ++it)
        xf[it] = *(const float4*)(X + ((size_t)(b * L_ + l0 + xr + it*8)) * DK_ + xc * 4);
#pragma unroll
    for (int it = 0; it < 8; ++it)
        wf[it] = *(const float4*)(W + (size_t)(xr + it*8) * DH_ + xc * 4);

    float acc[4][4][4];
#pragma unroll
    for (int i = 0; i < 4; ++i)
#pragma unroll
        for (int j = 0; j < 4; ++j)
#pragma unroll
            for (int c = 0; c < 4; ++c) acc[i][j][c] = 0.f;

    const uint32_t Xs_u = (uint32_t)__cvta_generic_to_shared(Xs);
    const uint32_t Ws_u = (uint32_t)__cvta_generic_to_shared(Ws);
    const uint32_t a_base = Xs_u + (uint32_t)(wm*64 + (lane & 15)) * (HSTR*2) + (lane >> 4) * 16;
    // B via trans: row = k (d), col byte = e*2
    const uint32_t bt_row = (uint32_t)(lane & 15);
    const uint32_t bt_col = (uint32_t)(wn*32 + ((lane >> 4) & 1) * 8) * 2;

    for (int d0 = 0; d0 < DK_; d0 += 64) {
#pragma unroll
        for (int it = 0; it < 16; ++it) {
            __half2 h01 = __floats2half2_rn(xf[it].x, xf[it].y);
            __half2 h23 = __floats2half2_rn(xf[it].z, xf[it].w);
            *(uint2*)(Xs + (xr + it*8) * HSTR + xc * 4) =
                make_uint2(*(uint32_t*)&h01, *(uint32_t*)&h23);
        }
#pragma unroll
        for (int it = 0; it < 8; ++it) {
            __half2 h01 = __floats2half2_rn(wf[it].x, wf[it].y);
            __half2 h23 = __floats2half2_rn(wf[it].z, wf[it].w);
            *(uint2*)(Ws + (xr + it*8) * HSTR + xc * 4) =
                make_uint2(*(uint32_t*)&h01, *(uint32_t*)&h23);
        }
        __syncthreads();
        if (d0 + 64 < DK_) {
#pragma unroll
            for (int it = 0; it < 16; ++it)
                xf[it] = *(const float4*)(X + ((size_t)(b * L_ + l0 + xr + it*8)) * DK_ + d0 + 64 + xc * 4);
#pragma unroll
            for (int it = 0; it < 8; ++it)
                wf[it] = *(const float4*)(W + (size_t)(d0 + 64 + xr + it*8) * DH_ + xc * 4);
        }
#pragma unroll
        for (int ks = 0; ks < 4; ++ks) {
            uint32_t a[4][4], bf[4][2];
#pragma unroll
            for (int mt = 0; mt < 4; ++mt)
                ldm_x4(a[mt], a_base + mt*16*(HSTR*2) + ks*32);
#pragma unroll
            for (int nb = 0; nb < 2; ++nb) {
                uint32_t bt[4];
                ldm_x4t(bt, Ws_u + (ks*16 + bt_row) * (HSTR*2) + bt_col + nb*32);
                bf[2*nb][0] = bt[0];   bf[2*nb][1] = bt[1];
                bf[2*nb+1][0] = bt[2]; bf[2*nb+1][1] = bt[3];
            }
#pragma unroll
            for (int mt = 0; mt < 4; ++mt)
#pragma unroll
                for (int nt = 0; nt < 4; ++nt)
                    mma_f16(acc[mt][nt], a[mt][0], a[mt][1], a[mt][2], a[mt][3],
                            bf[nt][0], bf[nt][1]);
        }
        __syncthreads();
    }
#pragma unroll
    for (int mt = 0; mt < 4; ++mt) {
        int l = l0 + wm*64 + mt*16 + grp;
#pragma unroll
        for (int nt = 0; nt < 4; ++nt) {
            int e = wn*32 + nt*8 + cp*2;
            *(__half2*)(O + ((size_t)bh*L_ + l)*DH_ + e) =
                __floats2half2_rn(acc[mt][nt][0], acc[mt][nt][1]);
            *(__half2*)(O + ((size_t)bh*L_ + l + 8)*DH_ + e) =
                __floats2half2_rn(acc[mt][nt][2], acc[mt][nt][3]);
        }
    }
}

// ---------------------------------------------------------------------------
// V projection (tf32 mma) — output feeds the result directly, keep precision.
// ---------------------------------------------------------------------------
__global__ __launch_bounds__(128) void vproj_kernel(
    const float* __restrict__ v_in, const float* __restrict__ wv)
{
    extern __shared__ float sm[];
    float* Xs = sm;             // [128][STR]
    float* Ws = sm + 128*STR;   // [64][STR] natural W rows

    const int bh = blockIdx.y, l0 = blockIdx.x * 128;
    const int b = bh / H_, h = bh % H_;
    const float* W = wv + (size_t)h * DK_ * DH_;

    const int tid = threadIdx.x, lane = tid & 31, wid = tid >> 5;
    const int wm = wid >> 1, wn = wid & 1;
    const int grp = lane >> 2, cp = lane & 3;
    const int xr = tid >> 4, xc = tid & 15;

    float4 xf[16], wf[8];
#pragma unroll
    for (int it = 0; it < 16; ++it)
        xf[it] = *(const float4*)(v_in + ((size_t)(b * L_ + l0 + xr + it*8)) * DK_ + xc * 4);
#pragma unroll
    for (int it = 0; it < 8; ++it)
        wf[it] = *(const float4*)(W + (size_t)(xr + it*8) * DH_ + xc * 4);

    float acc[4][4][4];
#pragma unroll
    for (int i = 0; i < 4; ++i)
#pragma unroll
        for (int j = 0; j < 4; ++j)
#pragma unroll
            for (int c = 0; c < 4; ++c) acc[i][j][c] = 0.f;

    for (int d0 = 0; d0 < DK_; d0 += 64) {
#pragma unroll
        for (int it = 0; it < 16; ++it)
            *(float4*)(Xs + (xr + it*8) * STR + xc * 4) = cvt4(xf[it]);
#pragma unroll
        for (int it = 0; it < 8; ++it)
            *(float4*)(Ws + (xr + it*8) * STR + xc * 4) = cvt4(wf[it]);
        __syncthreads();
        if (d0 + 64 < DK_) {
#pragma unroll
            for (int it = 0; it < 16; ++it)
                xf[it] = *(const float4*)(v_in + ((size_t)(b * L_ + l0 + xr + it*8)) * DK_ + d0 + 64 + xc * 4);
#pragma unroll
            for (int it = 0; it < 8; ++it)
                wf[it] = *(const float4*)(W + (size_t)(d0 + 64 + xr + it*8) * DH_ + xc * 4);
        }
#pragma unroll
        for (int ks = 0; ks < 8; ++ks) {
            float a[4][4];
#pragma unroll
            for (int mt = 0; mt < 4; ++mt) {
                const float* base = Xs + (wm*64 + mt*16 + grp) * STR + ks*8 + cp;
                a[mt][0] = base[0];       a[mt][2] = base[4];
                a[mt][1] = base[8*STR];   a[mt][3] = base[8*STR + 4];
            }
            float bf[4][2];
#pragma unroll
            for (int nt = 0; nt < 4; ++nt) {
                const float* base = Ws + (ks*8 + cp) * STR + wn*32 + nt*8 + grp;
                bf[nt][0] = base[0];      bf[nt][1] = base[4*STR];
            }
#pragma unroll
            for (int mt = 0; mt < 4; ++mt)
#pragma unroll
                for (int nt = 0; nt < 4; ++nt)
                    mma_tf32(acc[mt][nt], a[mt][0], a[mt][1], a[mt][2], a[mt][3],
                             bf[nt][0], bf[nt][1]);
        }
        __syncthreads();
    }
#pragma unroll
    for (int mt = 0; mt < 4; ++mt) {
        int l = l0 + wm*64 + mt*16 + grp;
#pragma unroll
        for (int nt = 0; nt < 4; ++nt) {
            int e = wn*32 + nt*8 + cp*2;
            *(float2*)(g_V + ((size_t)bh*L_ + l)*DH_ + e) =
                make_float2(acc[mt][nt][0], acc[mt][nt][1]);
            *(float2*)(g_V + ((size_t)bh*L_ + l + 8)*DH_ + e) =
                make_float2(acc[mt][nt][2], acc[mt][nt][3]);
        }
    }
}

// ---------------------------------------------------------------------------
// QK^T (fp16 mma + ldmatrix) + exp2 + coalesced P stores + column sums.
// Block 128q x 256k, 256 threads, warps 2x4, warp tile 64x32, two k-halves.
// ---------------------------------------------------------------------------
__global__ __launch_bounds__(256) void qk_kernel()
{
    extern __shared__ char smc[];
    __half* Qs = (__half*)smc;              // [128][HSTR]
    __half* Ks = Qs + 128*HSTR;             // [256][HSTR]
    float*  Cs = (float*)(Ks + 256*HSTR);   // [2][128]

    const int bh = blockIdx.z, qb = blockIdx.y, kb = blockIdx.x;
    const int q0 = qb * 128, k0 = kb * 256;
    const int tid = threadIdx.x, lane = tid & 31, wid = tid >> 5;
    const int wm = wid >> 2, wn = wid & 3;
    const int grp = lane >> 2, cp = lane & 3;

#pragma unroll
    for (int it = 0; it < 4; ++it) {
        int f = it * 256 + tid;
        int r = f >> 3, c8 = f & 7;
        cp16(Qs + r*HSTR + c8*8, g_Qh + ((size_t)bh*L_ + q0 + r)*DH_ + c8*8);
    }
#pragma unroll
    for (int it = 0; it < 8; ++it) {
        int f = it * 256 + tid;
        int r = f >> 3, c8 = f & 7;
        cp16(Ks + r*HSTR + c8*8, g_Kh + ((size_t)bh*L_ + k0 + r)*DH_ + c8*8);
    }
    cp_commit();
    cp_wait<0>();
    __syncthreads();

    const uint32_t Qs_u = (uint32_t)__cvta_generic_to_shared(Qs);
    const uint32_t Ks_u = (uint32_t)__cvta_generic_to_shared(Ks);
    const uint32_t a_base = Qs_u + (uint32_t)(wm*64 + (lane & 15)) * (HSTR*2) + (lane >> 4) * 16;
    const uint32_t b_base0 = Ks_u + (uint32_t)(wn*32 + ((lane >> 4) & 1)*8 + (lane & 7)) * (HSTR*2)
                                  + ((lane >> 3) & 1) * 16;

    const float rsc2 = 0.03188117935f;  // log2(e)/sqrt(2048)

#pragma unroll
    for (int kb2 = 0; kb2 < 2; ++kb2) {
        float acc[4][4][4];
#pragma unroll
        for (int i = 0; i < 4; ++i)
#pragma unroll
            for (int j = 0; j < 4; ++j)
#pragma unroll
                for (int c = 0; c < 4; ++c) acc[i][j][c] = 0.f;

        const uint32_t b_base = b_base0 + (uint32_t)kb2 * 128 * (HSTR*2);
#pragma unroll
        for (int ks = 0; ks < 4; ++ks) {
            uint32_t a[4][4], bf[4][2];
#pragma unroll
            for (int mt = 0; mt < 4; ++mt)
                ldm_x4(a[mt], a_base + mt*16*(HSTR*2) + ks*32);
#pragma unroll
            for (int np = 0; np < 2; ++np) {
                uint32_t bt[4];
                ldm_x4(bt, b_base + np*16*(HSTR*2) + ks*32);
                bf[2*np][0] = bt[0];   bf[2*np][1] = bt[1];
                bf[2*np+1][0] = bt[2]; bf[2*np+1][1] = bt[3];
            }
#pragma unroll
            for (int mt = 0; mt < 4; ++mt)
#pragma unroll
                for (int nt = 0; nt < 4; ++nt)
                    mma_f16(acc[mt][nt], a[mt][0], a[mt][1], a[mt][2], a[mt][3],
                            bf[nt][0], bf[nt][1]);
        }

        float cs0[4] = {0,0,0,0}, cs1[4] = {0,0,0,0};
        const uint32_t kcol = k0 + kb2*128 + wn*32 + cp*8;
#pragma unroll
        for (int mt = 0; mt < 4; ++mt) {
            int q = q0 + wm*64 + mt*16 + grp;
            uint32_t lo[4], hi[4];
#pragma unroll
            for (int nt = 0; nt < 4; ++nt) {
                float p0 = ex2(acc[mt][nt][0] * rsc2);
                float p1 = ex2(acc[mt][nt][1] * rsc2);
                float p2 = ex2(acc[mt][nt][2] * rsc2);
                float p3 = ex2(acc[mt][nt][3] * rsc2);
                cs0[nt] += p0 + p2;  cs1[nt] += p1 + p3;
                __half2 hl = __floats2half2_rn(p0, p1);
                __half2 hh = __floats2half2_rn(p2, p3);
                lo[nt] = *(uint32_t*)&hl;
                hi[nt] = *(uint32_t*)&hh;
            }
            quad_tr(lo, cp);
            quad_tr(hi, cp);
            __stcs((uint4*)(g_Ph + ((size_t)bh*L_ + q)*L_ + kcol),
                   make_uint4(lo[0], lo[1], lo[2], lo[3]));
            __stcs((uint4*)(g_Ph + ((size_t)bh*L_ + q + 8)*L_ + kcol),
                   make_uint4(hi[0], hi[1], hi[2], hi[3]));
        }
#pragma unroll
        for (int nt = 0; nt < 4; ++nt) {
            cs0[nt] += __shfl_xor_sync(0xffffffffu, cs0[nt], 4);
            cs0[nt] += __shfl_xor_sync(0xffffffffu, cs0[nt], 8);
            cs0[nt] += __shfl_xor_sync(0xffffffffu, cs0[nt], 16);
            cs1[nt] += __shfl_xor_sync(0xffffffffu, cs1[nt], 4);
            cs1[nt] += __shfl_xor_sync(0xffffffffu, cs1[nt], 8);
            cs1[nt] += __shfl_xor_sync(0xffffffffu, cs1[nt], 16);
        }
        if (lane < 4) {
#pragma unroll
            for (int nt = 0; nt < 4; ++nt) {
                Cs[wm*128 + wn*32 + nt*8 + lane*2]     = cs0[nt];
                Cs[wm*128 + wn*32 + nt*8 + lane*2 + 1] = cs1[nt];
            }
        }
        __syncthreads();
        if (tid < 128)
            g_Dp[((size_t)bh*QB_ + qb)*L_ + k0 + kb2*128 + tid] = Cs[tid] + Cs[128 + tid];
        __syncthreads();
    }
}

// ---------------------------------------------------------------------------
// Vt prep (folds D reduction): g_Vth[bh][e][k] = V[k][e] / D[k]
// ---------------------------------------------------------------------------
__global__ __launch_bounds__(256) void vprep_kernel()
{
    __shared__ float t[32][33];
    __shared__ float dv[32];
    const int bh = blockIdx.z;
    const int k0 = blockIdx.x * 32, e0 = blockIdx.y * 32;
    const int tx = threadIdx.x & 31, ty = threadIdx.x >> 5;
    if (threadIdx.x < 32) {
        float s = 0.f;
#pragma unroll
        for (int qt = 0; qt < QB_; ++qt)
            s += g_Dp[((size_t)bh*QB_ + qt)*L_ + k0 + threadIdx.x];
        dv[threadIdx.x] = 1.0f / s;
    }
    __syncthreads();
#pragma unroll
    for (int i = 0; i < 32; i += 8) {
        int k = k0 + ty + i;
        t[ty + i][tx] = g_V[((size_t)bh*L_ + k)*DH_ + e0 + tx] * dv[ty + i];
    }
    __syncthreads();
#pragma unroll
    for (int i = 0; i < 32; i += 8)
        g_Vth[((size_t)bh*DH_ + e0 + ty + i)*L_ + k0 + tx] = __float2half_rn(t[tx][ty + i]);
}

// ---------------------------------------------------------------------------
// PV (fp16 mma + ldmatrix): out[128q x 64e] = P @ Vt^T, k-chunks of 128,
// 2-stage cp.async.  256 threads, warps 4x2, warp tile 32q x 32e.  2 CTAs/SM.
// ---------------------------------------------------------------------------
__global__ __launch_bounds__(256, 2) void pv_kernel(float* __restrict__ out)
{
    extern __shared__ char smc[];
    const int STAGE = (128 + 64) * PHSTR;   // halfs per stage
    const int bh = blockIdx.y, q0 = blockIdx.x * 128;
    const int b = bh / H_, h = bh % H_;
    const int tid = threadIdx.x, lane = tid & 31, wid = tid >> 5;
    const int wm = wid >> 1, wn = wid & 1;
    const int grp = lane >> 2, cp = lane & 3;
    const int xr = tid >> 4, xc = tid & 15;

    const __half* Pbase = g_Ph + ((size_t)bh*L_ + q0)*L_;
    const __half* Vbase = g_Vth + (size_t)bh*DH_*L_;

    auto fill = [&](int s, int k0) {
        __half* Ps = (__half*)smc + s*STAGE;
        __half* Vs = Ps + 128*PHSTR;
#pragma unroll
        for (int it = 0; it < 8; ++it) {
            int r = xr + it*16;
            cp16(Ps + r*PHSTR + xc*8, Pbase + (size_t)r*L_ + k0 + xc*8);
        }
#pragma unroll
        for (int it = 0; it < 4; ++it) {
            int r = xr + it*16;
            cp16(Vs + r*PHSTR + xc*8, Vbase + (size_t)r*L_ + k0 + xc*8);
        }
        cp_commit();
    };

    float acc[2][4][4];
#pragma unroll
    for (int i = 0; i < 2; ++i)
#pragma unroll
        for (int j = 0; j < 4; ++j)
#pragma unroll
            for (int c = 0; c < 4; ++c) acc[i][j][c] = 0.f;

    fill(0, 0);

    const uint32_t a_lrow = (uint32_t)(wm*32 + (lane & 15));
    const uint32_t a_csel = (uint32_t)(lane >> 4) * 16;
    const uint32_t b_lrow = (uint32_t)(wn*32 + ((lane >> 4) & 1)*8 + (lane & 7));
    const uint32_t b_csel = (uint32_t)((lane >> 3) & 1) * 16;

    for (int it = 0; it < L_/128; ++it) {
        int s = it & 1;
        if (it + 1 < L_/128) { fill(1 - s, (it + 1) * 128); cp_wait<1>(); }
        else                 { cp_wait<0>(); }
        __syncthreads();

        const __half* Ps = (__half*)smc + s*STAGE;
        const __half* Vs = Ps + 128*PHSTR;
        const uint32_t Ps_u = (uint32_t)__cvta_generic_to_shared(Ps);
        const uint32_t Vs_u = (uint32_t)__cvta_generic_to_shared(Vs);
        const uint32_t a_base = Ps_u + a_lrow * (PHSTR*2) + a_csel;
        const uint32_t b_base = Vs_u + b_lrow * (PHSTR*2) + b_csel;

#pragma unroll
        for (int ks = 0; ks < 8; ++ks) {
            uint32_t a[2][4], bf[4][2];
#pragma unroll
            for (int mt = 0; mt < 2; ++mt)
                ldm_x4(a[mt], a_base + mt*16*(PHSTR*2) + ks*32);
#pragma unroll
            for (int np = 0; np < 2; ++np) {
                uint32_t bt[4];
                ldm_x4(bt, b_base + np*16*(PHSTR*2) + ks*32);
                bf[2*np][0] = bt[0];   bf[2*np][1] = bt[1];
                bf[2*np+1][0] = bt[2]; bf[2*np+1][1] = bt[3];
            }
#pragma unroll
            for (int mt = 0; mt < 2; ++mt)
#pragma unroll
                for (int nt = 0; nt < 4; ++nt)
                    mma_f16(acc[mt][nt], a[mt][0], a[mt][1], a[mt][2], a[mt][3],
                            bf[nt][0], bf[nt][1]);
        }
        __syncthreads();
    }
#pragma unroll
    for (int mt = 0; mt < 2; ++mt) {
        int q = q0 + wm*32 + mt*16 + grp;
#pragma unroll
        for (int nt = 0; nt < 4; ++nt) {
            int e = wn*32 + nt*8 + cp*2;
            *(float2*)(out + ((size_t)b*L_ + q)*(H_*DH_) + h*DH_ + e) =
                make_float2(acc[mt][nt][0], acc[mt][nt][1]);
            *(float2*)(out + ((size_t)b*L_ + q + 8)*(H_*DH_) + h*DH_ + e) =
                make_float2(acc[mt][nt][2], acc[mt][nt][3]);
        }
    }
}

// ---------------------------------------------------------------------------
extern "C" void kernel_launch(void* const* d_in, const int* in_sizes, int n_in,
                              void* d_out, int out_size)
{
    const float* keys    = (const float*)d_in[0];
    const float* queries = (const float*)d_in[1];
    const float* values  = (const float*)d_in[2];
    const float* WQ      = (const float*)d_in[3];
    const float* WK      = (const float*)d_in[4];
    const float* WV      = (const float*)d_in[5];
    float* out = (float*)d_out;

    const int QP_SMEM = (128 + 64)*HSTR*2;             // 27648
    const int VP_SMEM = (192*STR) * 4;                 // 52224
    const int QK_SMEM = (128 + 256)*HSTR*2 + 256*4;    // 56320
    const int PV_SMEM = 2*(128 + 64)*PHSTR*2;          // 104448

    cudaFuncSetAttribute(qkproj_kernel, cudaFuncAttributeMaxDynamicSharedMemorySize, QP_SMEM);
    cudaFuncSetAttribute(vproj_kernel,  cudaFuncAttributeMaxDynamicSharedMemorySize, VP_SMEM);
    cudaFuncSetAttribute(qk_kernel,     cudaFuncAttributeMaxDynamicSharedMemorySize, QK_SMEM);
    cudaFuncSetAttribute(pv_kernel,     cudaFuncAttributeMaxDynamicSharedMemorySize, PV_SMEM);

    qkproj_kernel<<<dim3(L_/128, BH_, 2), 128, QP_SMEM>>>(queries, keys, WQ, WK);
    vproj_kernel<<<dim3(L_/128, BH_), 128, VP_SMEM>>>(values, WV);
    qk_kernel<<<dim3(L_/256, L_/128, BH_), 256, QK_SMEM>>>();
    vprep_kernel<<<dim3(L_/32, DH_/32, BH_), 256>>>();
    pv_kernel<<<dim3(L_/128, BH_), 256, PV_SMEM>>>(out);
}

// round 10
// speedup vs baseline: 2.3029x; 1.1102x over previous
#include <cuda_runtime.h>
#include <cuda_fp16.h>
#include <cstdint>

#define B_  2
#define L_  2048
#define DK_ 512
#define H_  8
#define DH_ 64
#define BH_ (B_*H_)
#define QB_ (L_/128)
#define HSTR 72         // half smem stride for 64-wide tiles  (144 B)
#define PHSTR 136       // half smem stride for 128-wide tiles (272 B)

// ---- device scratch ----
__device__ __align__(256) __half g_Qh[BH_*L_*DH_];
__device__ __align__(256) __half g_Kh[BH_*L_*DH_];
__device__ __align__(256) float  g_V[BH_*L_*DH_];
__device__ __align__(256) __half g_Vh[BH_*L_*DH_];         // [bh][k][e] = V*Dinv (half)
__device__ __align__(256) __half g_Ph[(size_t)BH_*L_*L_];  // 128 MiB
__device__ __align__(256) float  g_Dp[BH_*QB_*L_];

__device__ __forceinline__ float ex2(float x) {
    float r; asm("ex2.approx.f32 %0, %1;" : "=f"(r) : "f"(x));
    return r;
}
__device__ __forceinline__ void mma_f16(float* d, uint32_t a0, uint32_t a1, uint32_t a2,
                                        uint32_t a3, uint32_t b0, uint32_t b1) {
    asm volatile("mma.sync.aligned.m16n8k16.row.col.f32.f16.f16.f32 "
                 "{%0,%1,%2,%3}, {%4,%5,%6,%7}, {%8,%9}, {%0,%1,%2,%3};"
                 : "+f"(d[0]), "+f"(d[1]), "+f"(d[2]), "+f"(d[3])
                 : "r"(a0), "r"(a1), "r"(a2), "r"(a3), "r"(b0), "r"(b1));
}
__device__ __forceinline__ void ldm_x4(uint32_t* r, uint32_t saddr) {
    asm volatile("ldmatrix.sync.aligned.m8n8.x4.shared.b16 {%0,%1,%2,%3}, [%4];"
                 : "=r"(r[0]), "=r"(r[1]), "=r"(r[2]), "=r"(r[3]) : "r"(saddr));
}
__device__ __forceinline__ void ldm_x4t(uint32_t* r, uint32_t saddr) {
    asm volatile("ldmatrix.sync.aligned.m8n8.x4.trans.shared.b16 {%0,%1,%2,%3}, [%4];"
                 : "=r"(r[0]), "=r"(r[1]), "=r"(r[2]), "=r"(r[3]) : "r"(saddr));
}
__device__ __forceinline__ void cp16(void* dst_smem, const void* src) {
    uint32_t d = (uint32_t)__cvta_generic_to_shared(dst_smem);
    asm volatile("cp.async.cg.shared.global [%0], [%1], 16;" :: "r"(d), "l"(src));
}
__device__ __forceinline__ void cp_commit() { asm volatile("cp.async.commit_group;"); }
template<int N> __device__ __forceinline__ void cp_wait() {
    asm volatile("cp.async.wait_group %0;" :: "n"(N));
}
// 4x4 u32 transpose across a lane quad (lanes differing in bits 0-1).
__device__ __forceinline__ void quad_tr(uint32_t x[4], int cp) {
    uint32_t s0 = (cp & 2) ? x[0] : x[2];
    uint32_t s1 = (cp & 2) ? x[1] : x[3];
    uint32_t r0 = __shfl_xor_sync(0xffffffffu, s0, 2);
    uint32_t r1 = __shfl_xor_sync(0xffffffffu, s1, 2);
    if (cp & 2) { x[0] = r0; x[1] = r1; } else { x[2] = r0; x[3] = r1; }
    uint32_t s2 = (cp & 1) ? x[0] : x[1];
    uint32_t s3 = (cp & 1) ? x[2] : x[3];
    uint32_t r2 = __shfl_xor_sync(0xffffffffu, s2, 1);
    uint32_t r3 = __shfl_xor_sync(0xffffffffu, s3, 1);
    if (cp & 1) { x[0] = r2; x[2] = r3; } else { x[1] = r2; x[3] = r3; }
}

// ---------------------------------------------------------------------------
// Unified projections (fp16 mma, fp32 accum).  A = X[128l x 64d] (fp16),
// B = W[d][e] via ldmatrix.trans.  Q,K -> half; V -> fp32.
// 128 threads, warps 2x2, warp tile 64l x 32e.
// ---------------------------------------------------------------------------
__global__ __launch_bounds__(128) void proj_kernel(
    const float* __restrict__ q_in, const float* __restrict__ k_in,
    const float* __restrict__ v_in, const float* __restrict__ wq,
    const float* __restrict__ wk,  const float* __restrict__ wv)
{
    extern __shared__ char smc[];
    __half* Xs = (__half*)smc;       // [128][HSTR]
    __half* Ws = Xs + 128*HSTR;      // [64][HSTR]  (natural W rows: d-major)

    const int mat = blockIdx.z, bh = blockIdx.y, l0 = blockIdx.x * 128;
    const int b = bh / H_, h = bh % H_;
    const float* X = (mat == 0) ? q_in : (mat == 1) ? k_in : v_in;
    const float* W = ((mat == 0) ? wq : (mat == 1) ? wk : wv) + (size_t)h * DK_ * DH_;

    const int tid = threadIdx.x, lane = tid & 31, wid = tid >> 5;
    const int wm = wid >> 1, wn = wid & 1;
    const int grp = lane >> 2, cp = lane & 3;
    const int xr = tid >> 4, xc = tid & 15;

    float4 xf[16], wf[8];
#pragma unroll
    for (int it = 0; it < 16; ++it)
        xf[it] = *(const float4*)(X + ((size_t)(b * L_ + l0 + xr + it*8)) * DK_ + xc * 4);
#pragma unroll
    for (int it = 0; it < 8; ++it)
        wf[it] = *(const float4*)(W + (size_t)(xr + it*8) * DH_ + xc * 4);

    float acc[4][4][4];
#pragma unroll
    for (int i = 0; i < 4; ++i)
#pragma unroll
        for (int j = 0; j < 4; ++j)
#pragma unroll
            for (int c = 0; c < 4; ++c) acc[i][j][c] = 0.f;

    const uint32_t Xs_u = (uint32_t)__cvta_generic_to_shared(Xs);
    const uint32_t Ws_u = (uint32_t)__cvta_generic_to_shared(Ws);
    const uint32_t a_base = Xs_u + (uint32_t)(wm*64 + (lane & 15)) * (HSTR*2) + (lane >> 4) * 16;
    const uint32_t bt_row = (uint32_t)(lane & 15);
    const uint32_t bt_col = (uint32_t)(wn*32 + ((lane >> 4) & 1) * 8) * 2;

    for (int d0 = 0; d0 < DK_; d0 += 64) {
#pragma unroll
        for (int it = 0; it < 16; ++it) {
            __half2 h01 = __floats2half2_rn(xf[it].x, xf[it].y);
            __half2 h23 = __floats2half2_rn(xf[it].z, xf[it].w);
            *(uint2*)(Xs + (xr + it*8) * HSTR + xc * 4) =
                make_uint2(*(uint32_t*)&h01, *(uint32_t*)&h23);
        }
#pragma unroll
        for (int it = 0; it < 8; ++it) {
            __half2 h01 = __floats2half2_rn(wf[it].x, wf[it].y);
            __half2 h23 = __floats2half2_rn(wf[it].z, wf[it].w);
            *(uint2*)(Ws + (xr + it*8) * HSTR + xc * 4) =
                make_uint2(*(uint32_t*)&h01, *(uint32_t*)&h23);
        }
        __syncthreads();
        if (d0 + 64 < DK_) {
#pragma unroll
            for (int it = 0; it < 16; ++it)
                xf[it] = *(const float4*)(X + ((size_t)(b * L_ + l0 + xr + it*8)) * DK_ + d0 + 64 + xc * 4);
#pragma unroll
            for (int it = 0; it < 8; ++it)
                wf[it] = *(const float4*)(W + (size_t)(d0 + 64 + xr + it*8) * DH_ + xc * 4);
        }
#pragma unroll
        for (int ks = 0; ks < 4; ++ks) {
            uint32_t a[4][4], bf[4][2];
#pragma unroll
            for (int mt = 0; mt < 4; ++mt)
                ldm_x4(a[mt], a_base + mt*16*(HSTR*2) + ks*32);
#pragma unroll
            for (int nb = 0; nb < 2; ++nb) {
                uint32_t bt[4];
                ldm_x4t(bt, Ws_u + (ks*16 + bt_row) * (HSTR*2) + bt_col + nb*32);
                bf[2*nb][0] = bt[0];   bf[2*nb][1] = bt[1];
                bf[2*nb+1][0] = bt[2]; bf[2*nb+1][1] = bt[3];
            }
#pragma unroll
            for (int mt = 0; mt < 4; ++mt)
#pragma unroll
                for (int nt = 0; nt < 4; ++nt)
                    mma_f16(acc[mt][nt], a[mt][0], a[mt][1], a[mt][2], a[mt][3],
                            bf[nt][0], bf[nt][1]);
        }
        __syncthreads();
    }
#pragma unroll
    for (int mt = 0; mt < 4; ++mt) {
        int l = l0 + wm*64 + mt*16 + grp;
#pragma unroll
        for (int nt = 0; nt < 4; ++nt) {
            int e = wn*32 + nt*8 + cp*2;
            if (mat < 2) {
                __half* O = (mat == 0) ? g_Qh : g_Kh;
                *(__half2*)(O + ((size_t)bh*L_ + l)*DH_ + e) =
                    __floats2half2_rn(acc[mt][nt][0], acc[mt][nt][1]);
                *(__half2*)(O + ((size_t)bh*L_ + l + 8)*DH_ + e) =
                    __floats2half2_rn(acc[mt][nt][2], acc[mt][nt][3]);
            } else {
                *(float2*)(g_V + ((size_t)bh*L_ + l)*DH_ + e) =
                    make_float2(acc[mt][nt][0], acc[mt][nt][1]);
                *(float2*)(g_V + ((size_t)bh*L_ + l + 8)*DH_ + e) =
                    make_float2(acc[mt][nt][2], acc[mt][nt][3]);
            }
        }
    }
}

// ---------------------------------------------------------------------------
// QK^T (fp16 mma + ldmatrix) + exp2 + coalesced P stores + column sums.
// Block 128q x 256k, 256 threads, warps 2x4, warp tile 64x32, two k-halves.
// 2 CTAs/SM.
// ---------------------------------------------------------------------------
__global__ __launch_bounds__(256, 2) void qk_kernel()
{
    extern __shared__ char smc[];
    __half* Qs = (__half*)smc;              // [128][HSTR]
    __half* Ks = Qs + 128*HSTR;             // [256][HSTR]
    float*  Cs = (float*)(Ks + 256*HSTR);   // [2][128]

    const int bh = blockIdx.z, qb = blockIdx.y, kb = blockIdx.x;
    const int q0 = qb * 128, k0 = kb * 256;
    const int tid = threadIdx.x, lane = tid & 31, wid = tid >> 5;
    const int wm = wid >> 2, wn = wid & 3;
    const int grp = lane >> 2, cp = lane & 3;

#pragma unroll
    for (int it = 0; it < 4; ++it) {
        int f = it * 256 + tid;
        int r = f >> 3, c8 = f & 7;
        cp16(Qs + r*HSTR + c8*8, g_Qh + ((size_t)bh*L_ + q0 + r)*DH_ + c8*8);
    }
#pragma unroll
    for (int it = 0; it < 8; ++it) {
        int f = it * 256 + tid;
        int r = f >> 3, c8 = f & 7;
        cp16(Ks + r*HSTR + c8*8, g_Kh + ((size_t)bh*L_ + k0 + r)*DH_ + c8*8);
    }
    cp_commit();
    cp_wait<0>();
    __syncthreads();

    const uint32_t Qs_u = (uint32_t)__cvta_generic_to_shared(Qs);
    const uint32_t Ks_u = (uint32_t)__cvta_generic_to_shared(Ks);
    const uint32_t a_base = Qs_u + (uint32_t)(wm*64 + (lane & 15)) * (HSTR*2) + (lane >> 4) * 16;
    const uint32_t b_base0 = Ks_u + (uint32_t)(wn*32 + ((lane >> 4) & 1)*8 + (lane & 7)) * (HSTR*2)
                                  + ((lane >> 3) & 1) * 16;

    const float rsc2 = 0.03188117935f;  // log2(e)/sqrt(2048)

#pragma unroll
    for (int kb2 = 0; kb2 < 2; ++kb2) {
        float acc[4][4][4];
#pragma unroll
        for (int i = 0; i < 4; ++i)
#pragma unroll
            for (int j = 0; j < 4; ++j)
#pragma unroll
                for (int c = 0; c < 4; ++c) acc[i][j][c] = 0.f;

        const uint32_t b_base = b_base0 + (uint32_t)kb2 * 128 * (HSTR*2);
#pragma unroll
        for (int ks = 0; ks < 4; ++ks) {
            uint32_t a[4][4], bf[4][2];
#pragma unroll
            for (int mt = 0; mt < 4; ++mt)
                ldm_x4(a[mt], a_base + mt*16*(HSTR*2) + ks*32);
#pragma unroll
            for (int np = 0; np < 2; ++np) {
                uint32_t bt[4];
                ldm_x4(bt, b_base + np*16*(HSTR*2) + ks*32);
                bf[2*np][0] = bt[0];   bf[2*np][1] = bt[1];
                bf[2*np+1][0] = bt[2]; bf[2*np+1][1] = bt[3];
            }
#pragma unroll
            for (int mt = 0; mt < 4; ++mt)
#pragma unroll
                for (int nt = 0; nt < 4; ++nt)
                    mma_f16(acc[mt][nt], a[mt][0], a[mt][1], a[mt][2], a[mt][3],
                            bf[nt][0], bf[nt][1]);
        }

        float cs0[4] = {0,0,0,0}, cs1[4] = {0,0,0,0};
        const uint32_t kcol = k0 + kb2*128 + wn*32 + cp*8;
#pragma unroll
        for (int mt = 0; mt < 4; ++mt) {
            int q = q0 + wm*64 + mt*16 + grp;
            uint32_t lo[4], hi[4];
#pragma unroll
            for (int nt = 0; nt < 4; ++nt) {
                float p0 = ex2(acc[mt][nt][0] * rsc2);
                float p1 = ex2(acc[mt][nt][1] * rsc2);
                float p2 = ex2(acc[mt][nt][2] * rsc2);
                float p3 = ex2(acc[mt][nt][3] * rsc2);
                cs0[nt] += p0 + p2;  cs1[nt] += p1 + p3;
                __half2 hl = __floats2half2_rn(p0, p1);
                __half2 hh = __floats2half2_rn(p2, p3);
                lo[nt] = *(uint32_t*)&hl;
                hi[nt] = *(uint32_t*)&hh;
            }
            quad_tr(lo, cp);
            quad_tr(hi, cp);
            __stcs((uint4*)(g_Ph + ((size_t)bh*L_ + q)*L_ + kcol),
                   make_uint4(lo[0], lo[1], lo[2], lo[3]));
            __stcs((uint4*)(g_Ph + ((size_t)bh*L_ + q + 8)*L_ + kcol),
                   make_uint4(hi[0], hi[1], hi[2], hi[3]));
        }
#pragma unroll
        for (int nt = 0; nt < 4; ++nt) {
            cs0[nt] += __shfl_xor_sync(0xffffffffu, cs0[nt], 4);
            cs0[nt] += __shfl_xor_sync(0xffffffffu, cs0[nt], 8);
            cs0[nt] += __shfl_xor_sync(0xffffffffu, cs0[nt], 16);
            cs1[nt] += __shfl_xor_sync(0xffffffffu, cs1[nt], 4);
            cs1[nt] += __shfl_xor_sync(0xffffffffu, cs1[nt], 8);
            cs1[nt] += __shfl_xor_sync(0xffffffffu, cs1[nt], 16);
        }
        if (lane < 4) {
#pragma unroll
            for (int nt = 0; nt < 4; ++nt) {
                Cs[wm*128 + wn*32 + nt*8 + lane*2]     = cs0[nt];
                Cs[wm*128 + wn*32 + nt*8 + lane*2 + 1] = cs1[nt];
            }
        }
        __syncthreads();
        if (tid < 128)
            g_Dp[((size_t)bh*QB_ + qb)*L_ + k0 + kb2*128 + tid] = Cs[tid] + Cs[128 + tid];
        __syncthreads();
    }
}

// ---------------------------------------------------------------------------
// V scale (no transpose): g_Vh[bh][k][e] = V[k][e] / D[k], half.
// grid (L_/128, BH_), 128 threads.
// ---------------------------------------------------------------------------
__global__ __launch_bounds__(128) void vprep_kernel()
{
    __shared__ float dv[128];
    const int bh = blockIdx.y, k0 = blockIdx.x * 128;
    const int tid = threadIdx.x;

    float s = 0.f;
#pragma unroll
    for (int qt = 0; qt < QB_; ++qt)
        s += g_Dp[((size_t)bh*QB_ + qt)*L_ + k0 + tid];
    dv[tid] = 1.0f / s;
    __syncthreads();

#pragma unroll
    for (int it = 0; it < 8; ++it) {
        int f = it * 128 + tid;          // 1024 chunks of 8 halfs
        int r = f >> 3, c = f & 7;
        float d = dv[r];
        const float* vp = g_V + ((size_t)bh*L_ + k0 + r)*DH_ + c*8;
        float4 v0 = *(const float4*)(vp);
        float4 v1 = *(const float4*)(vp + 4);
        __half2 h0 = __floats2half2_rn(v0.x*d, v0.y*d);
        __half2 h1 = __floats2half2_rn(v0.z*d, v0.w*d);
        __half2 h2 = __floats2half2_rn(v1.x*d, v1.y*d);
        __half2 h3 = __floats2half2_rn(v1.z*d, v1.w*d);
        *(uint4*)(g_Vh + ((size_t)bh*L_ + k0 + r)*DH_ + c*8) =
            make_uint4(*(uint32_t*)&h0, *(uint32_t*)&h1, *(uint32_t*)&h2, *(uint32_t*)&h3);
    }
}

// ---------------------------------------------------------------------------
// PV (fp16 mma): out[128q x 64e] = P @ V, V natural [k][e] via ldmatrix.trans.
// k-chunks of 128, 2-stage cp.async.  256 threads, warps 4x2,
// warp tile 32q x 32e.  2 CTAs/SM.
// ---------------------------------------------------------------------------
__global__ __launch_bounds__(256, 2) void pv_kernel(float* __restrict__ out)
{
    extern __shared__ char smc[];
    const int STAGE = 128*PHSTR + 128*HSTR;   // halfs per stage
    const int bh = blockIdx.y, q0 = blockIdx.x * 128;
    const int b = bh / H_, h = bh % H_;
    const int tid = threadIdx.x, lane = tid & 31, wid = tid >> 5;
    const int wm = wid >> 1, wn = wid & 1;
    const int grp = lane >> 2, cp = lane & 3;
    const int xr = tid >> 4, xc = tid & 15;

    const __half* Pbase = g_Ph + ((size_t)bh*L_ + q0)*L_;
    const __half* Vbase = g_Vh + (size_t)bh*L_*DH_;

    auto fill = [&](int s, int k0) {
        __half* Ps = (__half*)smc + s*STAGE;
        __half* Vs = Ps + 128*PHSTR;
#pragma unroll
        for (int it = 0; it < 8; ++it) {
            int r = xr + it*16;
            cp16(Ps + r*PHSTR + xc*8, Pbase + (size_t)r*L_ + k0 + xc*8);
        }
        // V tile: 128 k-rows x 64 e (natural layout)
#pragma unroll
        for (int it = 0; it < 4; ++it) {
            int f = it * 256 + tid;
            int r = f >> 3, c = f & 7;
            cp16(Vs + r*HSTR + c*8, Vbase + (size_t)(k0 + r)*DH_ + c*8);
        }
        cp_commit();
    };

    float acc[2][4][4];
#pragma unroll
    for (int i = 0; i < 2; ++i)
#pragma unroll
        for (int j = 0; j < 4; ++j)
#pragma unroll
            for (int c = 0; c < 4; ++c) acc[i][j][c] = 0.f;

    fill(0, 0);

    const uint32_t a_lrow = (uint32_t)(wm*32 + (lane & 15));
    const uint32_t a_csel = (uint32_t)(lane >> 4) * 16;
    const uint32_t bt_row = (uint32_t)(lane & 15);
    const uint32_t bt_col = (uint32_t)(wn*32 + ((lane >> 4) & 1) * 8) * 2;

    for (int it = 0; it < L_/128; ++it) {
        int s = it & 1;
        if (it + 1 < L_/128) { fill(1 - s, (it + 1) * 128); cp_wait<1>(); }
        else                 { cp_wait<0>(); }
        __syncthreads();

        const __half* Ps = (__half*)smc + s*STAGE;
        const uint32_t Ps_u = (uint32_t)__cvta_generic_to_shared(Ps);
        const uint32_t Vs_u = Ps_u + 128*PHSTR*2;
        const uint32_t a_base = Ps_u + a_lrow * (PHSTR*2) + a_csel;

#pragma unroll
        for (int ks = 0; ks < 8; ++ks) {
            uint32_t a[2][4], bf[4][2];
#pragma unroll
            for (int mt = 0; mt < 2; ++mt)
                ldm_x4(a[mt], a_base + mt*16*(PHSTR*2) + ks*32);
#pragma unroll
            for (int nb = 0; nb < 2; ++nb) {
                uint32_t bt[4];
                ldm_x4t(bt, Vs_u + (ks*16 + bt_row) * (HSTR*2) + bt_col + nb*32);
                bf[2*nb][0] = bt[0];   bf[2*nb][1] = bt[1];
                bf[2*nb+1][0] = bt[2]; bf[2*nb+1][1] = bt[3];
            }
#pragma unroll
            for (int mt = 0; mt < 2; ++mt)
#pragma unroll
                for (int nt = 0; nt < 4; ++nt)
                    mma_f16(acc[mt][nt], a[mt][0], a[mt][1], a[mt][2], a[mt][3],
                            bf[nt][0], bf[nt][1]);
        }
        __syncthreads();
    }
#pragma unroll
    for (int mt = 0; mt < 2; ++mt) {
        int q = q0 + wm*32 + mt*16 + grp;
#pragma unroll
        for (int nt = 0; nt < 4; ++nt) {
            int e = wn*32 + nt*8 + cp*2;
            *(float2*)(out + ((size_t)b*L_ + q)*(H_*DH_) + h*DH_ + e) =
                make_float2(acc[mt][nt][0], acc[mt][nt][1]);
            *(float2*)(out + ((size_t)b*L_ + q + 8)*(H_*DH_) + h*DH_ + e) =
                make_float2(acc[mt][nt][2], acc[mt][nt][3]);
        }
    }
}

// ---------------------------------------------------------------------------
extern "C" void kernel_launch(void* const* d_in, const int* in_sizes, int n_in,
                              void* d_out, int out_size)
{
    const float* keys    = (const float*)d_in[0];
    const float* queries = (const float*)d_in[1];
    const float* values  = (const float*)d_in[2];
    const float* WQ      = (const float*)d_in[3];
    const float* WK      = (const float*)d_in[4];
    const float* WV      = (const float*)d_in[5];
    float* out = (float*)d_out;

    const int QP_SMEM = (128 + 64)*HSTR*2;                   // 27648
    const int QK_SMEM = (128 + 256)*HSTR*2 + 256*4;          // 56320
    const int PV_SMEM = 2*(128*PHSTR + 128*HSTR)*2;          // 106496

    cudaFuncSetAttribute(proj_kernel, cudaFuncAttributeMaxDynamicSharedMemorySize, QP_SMEM);
    cudaFuncSetAttribute(qk_kernel,   cudaFuncAttributeMaxDynamicSharedMemorySize, QK_SMEM);
    cudaFuncSetAttribute(pv_kernel,   cudaFuncAttributeMaxDynamicSharedMemorySize, PV_SMEM);

    proj_kernel<<<dim3(L_/128, BH_, 3), 128, QP_SMEM>>>(queries, keys, values, WQ, WK, WV);
    qk_kernel<<<dim3(L_/256, L_/128, BH_), 256, QK_SMEM>>>();
    vprep_kernel<<<dim3(L_/128, BH_), 128>>>();
    pv_kernel<<<dim3(L_/128, BH_), 256, PV_SMEM>>>(out);
}